// round 2
// baseline (speedup 1.0000x reference)
#include <cuda_runtime.h>

// Problem constants
#define B_  4
#define S_  512
#define D_  768
#define H_  12
#define DH_ 64
#define F_  2048

// ---------------- scratch (device globals; no allocations allowed) ----------
__device__ float g_WOV [H_ * D_ * D_];   // [h][m][o]
__device__ float g_M1  [H_ * D_ * F_];   // [h][m][f] = W_OV[h] @ W_enc^T
__device__ float g_A1  [H_ * F_ * D_];   // [h][f][m] = W_enc @ W_OV[h]^T
__device__ float g_vw  [H_ * F_ * F_];   // [h][f][g] masked
__device__ float g_xln [B_ * S_ * D_];
__device__ float g_upln[B_ * S_ * F_];
__device__ float g_Y   [B_ * H_ * S_ * F_]; // [b][h][k][f]
__device__ float g_c   [D_];
__device__ float g_bias0[F_];
__device__ float g_e   [F_];
__device__ int   g_maskmode;             // 0=uint8, 1=int32, 2=float32

// ---------------- mask dtype detector ---------------------------------------
__global__ void detect_mask_k(const unsigned char* __restrict__ m) {
    if (threadIdx.x != 0 || blockIdx.x != 0) return;
    int sawF = 0, sawB = 0;
    for (int i = 0; i < 65536; i++) {
        unsigned char v = m[i];
        if (v == 63 || v == 128) sawF = 1;         // float32 1.0f byte pattern
        else if (v != 0 && (i & 3) != 0) sawB = 1; // bool bytes off 4-alignment
    }
    g_maskmode = sawF ? 2 : (sawB ? 0 : 1);
}

// ---------------- elementwise prep: x_ln, up_ln, zero c ----------------------
__global__ void prep_k(const float* __restrict__ act,
                       const float* __restrict__ pf,
                       const float* __restrict__ lns) {
    long i = (long)blockIdx.x * blockDim.x + threadIdx.x;
    if (i < (long)B_ * S_ * F_) {
        g_upln[i] = pf[i] / lns[i / F_];
    }
    if (i < (long)B_ * S_ * D_) {
        g_xln[i] = act[i] / lns[i / D_];
    }
    if (i < D_) g_c[i] = 0.f;
}

// ---------------- c[d] = sum_{h,m} W_OV[h,m,d] * up_b_dec[m] ----------------
__global__ void c_k(const float* __restrict__ upb) {
    int d = blockIdx.x * 256 + threadIdx.x;   // 3 blocks x 256 = 768
    int h = blockIdx.y;
    if (d >= D_) return;
    const float* base = g_WOV + (long)h * D_ * D_;
    float s = 0.f;
    for (int m = 0; m < D_; m++) s += base[(long)m * D_ + d] * upb[m];
    atomicAdd(&g_c[d], s);
}

// -------- bias0[f] = b_enc[f] - (W_enc@b_dec)[f];  e[f] = (W_enc@c)[f] -------
__global__ void bias_vec_k(const float* __restrict__ W_enc,
                           const float* __restrict__ b_enc,
                           const float* __restrict__ b_dec) {
    int f = blockIdx.x * 256 + threadIdx.x;
    if (f >= F_) return;
    const float* row = W_enc + (long)f * D_;
    float s0 = 0.f, s1 = 0.f;
    for (int d = 0; d < D_; d++) {
        float w = row[d];
        s0 += w * b_dec[d];
        s1 += w * g_c[d];
    }
    g_bias0[f] = b_enc[f] - s0;
    g_e[f] = s1;
}

// ---------------- final epilogue: out += bias0[f] + e[f]/ln_scale ------------
__global__ void finish_k(float* __restrict__ out, const float* __restrict__ lns) {
    long i = (long)blockIdx.x * blockDim.x + threadIdx.x;
    if (i >= (long)B_ * S_ * F_) return;
    int f = (int)(i & (F_ - 1));          // F = 2048
    long row = i >> 11;                    // b*S + q
    out[i] += g_bias0[f] + g_e[f] / lns[row];
}

// ---------------- tiled SGEMM: 128x128x8, 8x8 per thread, 256 threads --------
// AMODE 0: A is row-major [M,K] with lda.
// AMODE 1: A is probs[b]: element (m,k) -> A[(k>>9)*S*S + m*S + (k&511)]
// TB 0: B row-major [K,N]; TB 1: C = A * B^T with B row-major [N,K].
// All M,N multiples of 128 and K multiples of 8 in this problem: no bounds checks.
constexpr int BM = 128, BN = 128, BKK = 8, TM = 8, TN = 8;

template<int AMODE, int TB, int ACC, int MASKEPI>
__global__ __launch_bounds__(256)
void sgemm_k(const float* __restrict__ A, const float* __restrict__ B,
             float* __restrict__ C,
             int K, int lda, int ldb, int ldc, int Hdim,
             long sAb, long sAh, long sBb, long sBh, long sCb, long sCh,
             const unsigned char* __restrict__ mask) {
    const int zb = blockIdx.z / Hdim;
    const int zh = blockIdx.z % Hdim;
    A += zb * sAb + zh * sAh;
    B += zb * sBb + zh * sBh;
    C += zb * sCb + zh * sCh;

    __shared__ float As[BKK][BM + 4];
    __shared__ float Bs[BKK][BN + 4];

    const int tid = threadIdx.x;
    const int tx = tid & 15;
    const int ty = tid >> 4;
    const int row0 = blockIdx.y * BM;
    const int col0 = blockIdx.x * BN;

    const int aRow = tid >> 1;            // 0..127
    const int aCol = (tid & 1) << 2;      // 0 or 4
    int bR, bC;
    if (TB) { bR = tid >> 1; bC = (tid & 1) << 2; }    // n, k-off
    else    { bR = tid >> 5; bC = (tid & 31) << 2; }   // k, n-off

    float acc[TM][TN];
    #pragma unroll
    for (int i = 0; i < TM; i++)
        #pragma unroll
        for (int j = 0; j < TN; j++) acc[i][j] = 0.f;

    for (int k0 = 0; k0 < K; k0 += BKK) {
        float4 av;
        if (AMODE == 0) {
            av = *reinterpret_cast<const float4*>(A + (long)(row0 + aRow) * lda + k0 + aCol);
        } else {
            int kk = k0 + aCol;
            av = *reinterpret_cast<const float4*>(
                A + (long)(kk >> 9) * (S_ * S_) + (long)(row0 + aRow) * S_ + (kk & (S_ - 1)));
        }
        As[aCol + 0][aRow] = av.x;
        As[aCol + 1][aRow] = av.y;
        As[aCol + 2][aRow] = av.z;
        As[aCol + 3][aRow] = av.w;

        if (TB) {
            float4 bv = *reinterpret_cast<const float4*>(B + (long)(col0 + bR) * ldb + k0 + bC);
            Bs[bC + 0][bR] = bv.x;
            Bs[bC + 1][bR] = bv.y;
            Bs[bC + 2][bR] = bv.z;
            Bs[bC + 3][bR] = bv.w;
        } else {
            float4 bv = *reinterpret_cast<const float4*>(B + (long)(k0 + bR) * ldb + col0 + bC);
            *reinterpret_cast<float4*>(&Bs[bR][bC]) = bv;
        }
        __syncthreads();

        #pragma unroll
        for (int kk = 0; kk < BKK; kk++) {
            float a[TM], bb[TN];
            #pragma unroll
            for (int i = 0; i < TM; i++) a[i] = As[kk][ty * TM + i];
            #pragma unroll
            for (int j = 0; j < TN; j++) bb[j] = Bs[kk][tx * TN + j];
            #pragma unroll
            for (int i = 0; i < TM; i++)
                #pragma unroll
                for (int j = 0; j < TN; j++) acc[i][j] += a[i] * bb[j];
        }
        __syncthreads();
    }

    const int mode = MASKEPI ? g_maskmode : 0;
    #pragma unroll
    for (int i = 0; i < TM; i++) {
        long r = row0 + ty * TM + i;
        #pragma unroll
        for (int j = 0; j < TN; j++) {
            long cc = col0 + tx * TN + j;
            float v = acc[i][j];
            if (MASKEPI) {
                long mi = r * F_ + cc;
                float mv;
                if (mode == 0)      mv = ((const unsigned char*)mask)[mi] ? 1.f : 0.f;
                else if (mode == 1) mv = ((const int*)mask)[mi] ? 1.f : 0.f;
                else                mv = (((const float*)mask)[mi] != 0.f) ? 1.f : 0.f;
                v *= mv;
            }
            long ci = r * ldc + cc;
            if (ACC) C[ci] += v;
            else     C[ci] = v;
        }
    }
}

// ---------------------------------------------------------------------------
extern "C" void kernel_launch(void* const* d_in, const int* in_sizes, int n_in,
                              void* d_out, int out_size) {
    (void)in_sizes; (void)n_in; (void)out_size;
    const float* act   = (const float*)d_in[0];   // initial_act [B,S,D]
    const float* lns   = (const float*)d_in[1];   // ln_scale [B,S,1]
    const float* probs = (const float*)d_in[2];   // [B,H,S,S]
    const float* pf    = (const float*)d_in[3];   // pruned_features [B,S,F]
    const float* W_O   = (const float*)d_in[4];   // [H,DH,D]
    const float* W_V   = (const float*)d_in[5];   // [H,D,DH]
    const float* W_enc = (const float*)d_in[6];   // [F,D]
    const float* b_enc = (const float*)d_in[7];   // [F]
    const float* b_dec = (const float*)d_in[8];   // [D]
    const float* W_dec = (const float*)d_in[9];   // [D,F]
    const float* upb   = (const float*)d_in[10];  // up_b_dec [D]
    const unsigned char* mask = (const unsigned char*)d_in[11]; // [F,F] dtype sniffed
    float* out = (float*)d_out;                    // [B,S,F]

    float *WOV, *M1, *A1, *vw, *xln, *upln, *Y;
    cudaGetSymbolAddress((void**)&WOV,  g_WOV);
    cudaGetSymbolAddress((void**)&M1,   g_M1);
    cudaGetSymbolAddress((void**)&A1,   g_A1);
    cudaGetSymbolAddress((void**)&vw,   g_vw);
    cudaGetSymbolAddress((void**)&xln,  g_xln);
    cudaGetSymbolAddress((void**)&upln, g_upln);
    cudaGetSymbolAddress((void**)&Y,    g_Y);

    const long DD = (long)D_ * D_;
    const long DF = (long)D_ * F_;
    const long FF = (long)F_ * F_;
    const long SF = (long)S_ * F_;
    const long SD = (long)S_ * D_;
    const long SS = (long)S_ * S_;

    detect_mask_k<<<1, 32>>>(mask);

    {
        long tot = (long)B_ * S_ * F_;
        prep_k<<<(int)((tot + 255) / 256), 256>>>(act, pf, lns);
    }

    // 1) W_OV[h] = W_V[h] (768x64) @ W_O[h] (64x768)   NN
    sgemm_k<0, 0, 0, 0><<<dim3(D_ / BN, D_ / BM, H_), 256>>>(
        W_V, W_O, WOV, DH_, DH_, D_, D_, H_,
        0, (long)D_ * DH_, 0, (long)DH_ * D_, 0, DD, nullptr);

    // small bias vectors (need W_OV)
    c_k<<<dim3(3, H_), 256>>>(upb);
    bias_vec_k<<<F_ / 256, 256>>>(W_enc, b_enc, b_dec);

    // 2) M1[h] = W_OV[h] (768x768) @ W_enc^T (768x2048)   NT
    sgemm_k<0, 1, 0, 0><<<dim3(F_ / BN, D_ / BM, H_), 256>>>(
        WOV, W_enc, M1, D_, D_, D_, F_, H_,
        0, DD, 0, 0, 0, DF, nullptr);

    // 3) A1[h] = W_enc (2048x768) @ W_OV[h]^T (768x768)   NT
    sgemm_k<0, 1, 0, 0><<<dim3(D_ / BN, F_ / BM, H_), 256>>>(
        W_enc, WOV, A1, D_, D_, D_, D_, H_,
        0, 0, 0, DD, 0, (long)F_ * D_, nullptr);

    // 4) vw[h] = (A1[h] (2048x768) @ W_dec (768x2048)) * mask   NN + mask epi
    sgemm_k<0, 0, 0, 1><<<dim3(F_ / BN, F_ / BM, H_), 256>>>(
        A1, W_dec, vw, D_, D_, F_, F_, H_,
        0, (long)F_ * D_, 0, 0, 0, FF, mask);

    // 5a) Y[b,h] = x_ln[b] (512x768) @ M1[h] (768x2048)   NN, init
    sgemm_k<0, 0, 0, 0><<<dim3(F_ / BN, S_ / BM, B_ * H_), 256>>>(
        xln, M1, Y, D_, D_, F_, F_, H_,
        SD, 0, 0, DF, (long)H_ * SF, SF, nullptr);

    // 5b) Y[b,h] += up_ln[b] (512x2048) @ vw[h]^T (2048x2048)   NT, acc
    sgemm_k<0, 1, 1, 0><<<dim3(F_ / BN, S_ / BM, B_ * H_), 256>>>(
        upln, vw, Y, F_, F_, F_, F_, H_,
        SF, 0, 0, FF, (long)H_ * SF, SF, nullptr);

    // 6) out[b] = sum_h probs[b,h] @ Y[b,h]  as one GEMM, K = H*S = 6144
    sgemm_k<1, 0, 0, 0><<<dim3(F_ / BN, S_ / BM, B_), 256>>>(
        probs, Y, out, H_ * S_, S_, F_, F_, 1,
        (long)H_ * SS, 0, (long)H_ * SF, 0, SF, 0, nullptr);

    // 7) out += bias0[f] + e[f] / ln_scale[b,q]
    {
        long tot = (long)B_ * S_ * F_;
        finish_k<<<(int)((tot + 255) / 256), 256>>>(out, lns);
    }
}

// round 3
// speedup vs baseline: 1.4212x; 1.4212x over previous
#include <cuda_runtime.h>

// Problem constants
#define B_  4
#define S_  512
#define D_  768
#define H_  12
#define DH_ 64
#define F_  2048
#define BS_ (B_ * S_)          // 2048
#define NNZCAP 262144          // cap on mask nonzeros (expected ~210K, >100 sigma margin)

// ---------------- scratch (device globals; no allocations allowed) ----------
__device__ float g_WOV  [H_ * D_ * D_];    // [h][m][o]
__device__ float g_A1   [H_ * F_ * D_];    // [h][f][m] = W_enc @ W_OV[h]^T  (== M1^T)
__device__ float g_xln  [B_ * S_ * D_];
__device__ float g_uplnT[F_ * BS_];        // [g][bk]  transposed up_ln
__device__ float g_Y    [B_ * H_ * S_ * F_]; // [b][h][k][f]
__device__ float g_vwval[H_ * NNZCAP];     // compact masked vw values
__device__ int   g_slot [(long)F_ * F_];   // (f,g) -> compact index or -1
__device__ int   g_gidx [NNZCAP];          // compact -> g
__device__ int   g_cnt  [F_];
__device__ int   g_rowptr[F_ + 1];
__device__ float g_c    [D_];
__device__ float g_bias0[F_];
__device__ float g_e    [F_];
__device__ int   g_maskmode;               // 0=uint8, 1=int32, 2=float32

// ---------------- mask dtype detector ---------------------------------------
__global__ void detect_mask_k(const unsigned char* __restrict__ m) {
    if (threadIdx.x != 0 || blockIdx.x != 0) return;
    int sawF = 0, sawB = 0;
    for (int i = 0; i < 65536; i++) {
        unsigned char v = m[i];
        if (v == 63 || v == 128) sawF = 1;         // float32 1.0f byte pattern
        else if (v != 0 && (i & 3) != 0) sawB = 1; // bool bytes off 4-alignment
    }
    g_maskmode = sawF ? 2 : (sawB ? 0 : 1);
}

__device__ __forceinline__ int mask_nz(const unsigned char* m, long idx, int mode) {
    if (mode == 0) return m[idx] != 0;
    if (mode == 1) return ((const int*)m)[idx] != 0;
    return ((const float*)m)[idx] != 0.f;
}

// ---------------- mask CSR builders -----------------------------------------
// warp per f: count nonzeros
__global__ void count_k(const unsigned char* __restrict__ m) {
    int w = (blockIdx.x * blockDim.x + threadIdx.x) >> 5;
    int lane = threadIdx.x & 31;
    if (w >= F_) return;
    int mode = g_maskmode;
    int cnt = 0;
    for (int g0 = 0; g0 < F_; g0 += 32) {
        int v = mask_nz(m, (long)w * F_ + g0 + lane, mode);
        cnt += __popc(__ballot_sync(0xffffffffu, v));
    }
    if (lane == 0) g_cnt[w] = cnt;
}

// single block exclusive scan of g_cnt -> g_rowptr
__global__ void scan_k() {
    __shared__ int part[256];
    int t = threadIdx.x;
    int base = t * 8;
    int s = 0;
    for (int i = 0; i < 8; i++) s += g_cnt[base + i];
    part[t] = s;
    __syncthreads();
    if (t == 0) {
        int r = 0;
        for (int i = 0; i < 256; i++) { int v = part[i]; part[i] = r; r += v; }
        g_rowptr[F_] = r;
    }
    __syncthreads();
    int r = part[t];
    for (int i = 0; i < 8; i++) { g_rowptr[base + i] = r; r += g_cnt[base + i]; }
}

// warp per f: ordered compaction -> g_gidx, g_slot
__global__ void fill_k(const unsigned char* __restrict__ m) {
    int w = (blockIdx.x * blockDim.x + threadIdx.x) >> 5;
    int lane = threadIdx.x & 31;
    if (w >= F_) return;
    int mode = g_maskmode;
    int base = g_rowptr[w];
    unsigned lt = (1u << lane) - 1u;
    for (int g0 = 0; g0 < F_; g0 += 32) {
        int g = g0 + lane;
        int v = mask_nz(m, (long)w * F_ + g, mode);
        unsigned bal = __ballot_sync(0xffffffffu, v);
        int pos = base + __popc(bal & lt);
        int slot = (v && pos < NNZCAP) ? pos : -1;
        g_slot[(long)w * F_ + g] = slot;
        if (slot >= 0) g_gidx[slot] = g;
        base += __popc(bal);
    }
}

// ---------------- prep: x_ln + zero c ---------------------------------------
__global__ void prep_x_k(const float* __restrict__ act, const float* __restrict__ lns) {
    long i = (long)blockIdx.x * blockDim.x + threadIdx.x;
    if (i < (long)B_ * S_ * D_) g_xln[i] = act[i] / lns[i / D_];
    if (i < D_) g_c[i] = 0.f;
}

// ---------------- prep: tiled transpose pf/ln -> up_lnT[g][bk] --------------
__global__ void prep_upT_k(const float* __restrict__ pf, const float* __restrict__ lns) {
    __shared__ float tile[32][33];
    int tx = threadIdx.x, ty = threadIdx.y;      // 32 x 8
    int g = blockIdx.x * 32 + tx;
    int bk0 = blockIdx.y * 32;
    #pragma unroll
    for (int i = 0; i < 32; i += 8) {
        int bk = bk0 + ty + i;
        tile[ty + i][tx] = pf[(long)bk * F_ + g] / lns[bk];
    }
    __syncthreads();
    int gOut0 = blockIdx.x * 32;
    int bkOut = bk0 + tx;
    #pragma unroll
    for (int i = 0; i < 32; i += 8) {
        g_uplnT[(long)(gOut0 + ty + i) * BS_ + bkOut] = tile[tx][ty + i];
    }
}

// ---------------- c[d] = sum_{h,m} W_OV[h,m,d] * up_b_dec[m] ----------------
__global__ void c_k(const float* __restrict__ upb) {
    int d = blockIdx.x * 256 + threadIdx.x;   // 3 x 256 = 768
    int h = blockIdx.y;
    int m0 = blockIdx.z * 96;
    if (d >= D_) return;
    const float* base = g_WOV + (long)h * D_ * D_;
    float s = 0.f;
    for (int m = m0; m < m0 + 96; m++) s += base[(long)m * D_ + d] * upb[m];
    atomicAdd(&g_c[d], s);
}

// -------- bias0[f] = b_enc[f] - (W_enc@b_dec)[f];  e[f] = (W_enc@c)[f] -------
__global__ void bias_vec_k(const float* __restrict__ W_enc,
                           const float* __restrict__ b_enc,
                           const float* __restrict__ b_dec) {
    int f = blockIdx.x * 256 + threadIdx.x;
    if (f >= F_) return;
    const float* row = W_enc + (long)f * D_;
    float s0 = 0.f, s1 = 0.f;
    for (int d = 0; d < D_; d++) {
        float w = row[d];
        s0 += w * b_dec[d];
        s1 += w * g_c[d];
    }
    g_bias0[f] = b_enc[f] - s0;
    g_e[f] = s1;
}

// ---------------- final epilogue: out += bias0[f] + e[f]/ln_scale ------------
__global__ void finish_k(float* __restrict__ out, const float* __restrict__ lns) {
    long i = (long)blockIdx.x * blockDim.x + threadIdx.x;
    if (i >= (long)B_ * S_ * F_) return;
    int f = (int)(i & (F_ - 1));
    long row = i >> 11;
    out[i] += g_bias0[f] + g_e[f] / lns[row];
}

// ---------------- tiled SGEMM: 128x128x8, 8x8 per thread, 256 threads --------
// AMODE 0: A row-major [M,K]. AMODE 1: A = probs[b], (m,k)->A[(k>>9)*S*S+m*S+(k&511)]
// TB 0: B row-major [K,N].  TB 1: C = A*B^T, B row-major [N,K].
// OUTMODE 0: C = acc.  2: scatter masked entries to g_vwval via g_slot (C unused).
constexpr int BM = 128, BN = 128, BKK = 8, TM = 8, TN = 8;

template<int AMODE, int TB, int OUTMODE>
__global__ __launch_bounds__(256)
void sgemm_k(const float* __restrict__ A, const float* __restrict__ B,
             float* __restrict__ C,
             int K, int lda, int ldb, int ldc, int Hdim,
             long sAb, long sAh, long sBb, long sBh, long sCb, long sCh) {
    const int zb = blockIdx.z / Hdim;
    const int zh = blockIdx.z % Hdim;
    A += zb * sAb + zh * sAh;
    B += zb * sBb + zh * sBh;
    C += zb * sCb + zh * sCh;

    __shared__ float As[BKK][BM + 4];
    __shared__ float Bs[BKK][BN + 4];

    const int tid = threadIdx.x;
    const int tx = tid & 15;
    const int ty = tid >> 4;
    const int row0 = blockIdx.y * BM;
    const int col0 = blockIdx.x * BN;

    const int aRow = tid >> 1;
    const int aCol = (tid & 1) << 2;
    int bR, bC;
    if (TB) { bR = tid >> 1; bC = (tid & 1) << 2; }
    else    { bR = tid >> 5; bC = (tid & 31) << 2; }

    float acc[TM][TN];
    #pragma unroll
    for (int i = 0; i < TM; i++)
        #pragma unroll
        for (int j = 0; j < TN; j++) acc[i][j] = 0.f;

    for (int k0 = 0; k0 < K; k0 += BKK) {
        float4 av;
        if (AMODE == 0) {
            av = *reinterpret_cast<const float4*>(A + (long)(row0 + aRow) * lda + k0 + aCol);
        } else {
            int kk = k0 + aCol;
            av = *reinterpret_cast<const float4*>(
                A + (long)(kk >> 9) * (S_ * S_) + (long)(row0 + aRow) * S_ + (kk & (S_ - 1)));
        }
        As[aCol + 0][aRow] = av.x;
        As[aCol + 1][aRow] = av.y;
        As[aCol + 2][aRow] = av.z;
        As[aCol + 3][aRow] = av.w;

        if (TB) {
            float4 bv = *reinterpret_cast<const float4*>(B + (long)(col0 + bR) * ldb + k0 + bC);
            Bs[bC + 0][bR] = bv.x;
            Bs[bC + 1][bR] = bv.y;
            Bs[bC + 2][bR] = bv.z;
            Bs[bC + 3][bR] = bv.w;
        } else {
            float4 bv = *reinterpret_cast<const float4*>(B + (long)(k0 + bR) * ldb + col0 + bC);
            *reinterpret_cast<float4*>(&Bs[bR][bC]) = bv;
        }
        __syncthreads();

        #pragma unroll
        for (int kk = 0; kk < BKK; kk++) {
            float a[TM], bb[TN];
            #pragma unroll
            for (int i = 0; i < TM; i++) a[i] = As[kk][ty * TM + i];
            #pragma unroll
            for (int j = 0; j < TN; j++) bb[j] = Bs[kk][tx * TN + j];
            #pragma unroll
            for (int i = 0; i < TM; i++)
                #pragma unroll
                for (int j = 0; j < TN; j++) acc[i][j] += a[i] * bb[j];
        }
        __syncthreads();
    }

    #pragma unroll
    for (int i = 0; i < TM; i++) {
        long r = row0 + ty * TM + i;
        #pragma unroll
        for (int j = 0; j < TN; j++) {
            long cc = col0 + tx * TN + j;
            if (OUTMODE == 2) {
                int s = g_slot[r * F_ + cc];
                if (s >= 0) g_vwval[(long)zh * NNZCAP + s] = acc[i][j];
            } else {
                C[r * ldc + cc] = acc[i][j];
            }
        }
    }
}

// ---------------- spMM: Y[b,h,k,f] += sum_j up_lnT[gidx[j], bk] * vwval[h,j] -
// block: 256 bk-cols x FT f-rows x HT heads
constexpr int FT = 16, HT = 4;

__global__ __launch_bounds__(256, 2)
void spmm_k() {
    const int t  = threadIdx.x;
    const int bk = blockIdx.x * 256 + t;
    const int f0 = blockIdx.y * FT;
    const int h0 = blockIdx.z * HT;

    float acc[FT][HT];
    #pragma unroll
    for (int i = 0; i < FT; i++)
        #pragma unroll
        for (int hh = 0; hh < HT; hh++) acc[i][hh] = 0.f;

    #pragma unroll 1
    for (int fi = 0; fi < FT; fi++) {
        const int f = f0 + fi;
        int j  = g_rowptr[f];
        const int je = g_rowptr[f + 1];
        for (; j + 3 < je; j += 4) {
            int   g0 = g_gidx[j+0], g1 = g_gidx[j+1], g2 = g_gidx[j+2], g3 = g_gidx[j+3];
            float x0 = g_uplnT[(long)g0 * BS_ + bk];
            float x1 = g_uplnT[(long)g1 * BS_ + bk];
            float x2 = g_uplnT[(long)g2 * BS_ + bk];
            float x3 = g_uplnT[(long)g3 * BS_ + bk];
            #pragma unroll
            for (int hh = 0; hh < HT; hh++) {
                const float* vp = g_vwval + (long)(h0 + hh) * NNZCAP + j;
                acc[fi][hh] += x0 * vp[0];
                acc[fi][hh] += x1 * vp[1];
                acc[fi][hh] += x2 * vp[2];
                acc[fi][hh] += x3 * vp[3];
            }
        }
        for (; j < je; j++) {
            int g = g_gidx[j];
            float x = g_uplnT[(long)g * BS_ + bk];
            #pragma unroll
            for (int hh = 0; hh < HT; hh++)
                acc[fi][hh] += x * g_vwval[(long)(h0 + hh) * NNZCAP + j];
        }
    }

    const int b = bk >> 9, k = bk & (S_ - 1);
    #pragma unroll
    for (int hh = 0; hh < HT; hh++) {
        long base = (((long)(b * H_ + h0 + hh)) * S_ + k) * F_ + f0;
        #pragma unroll
        for (int fi = 0; fi < FT; fi += 4) {
            float4 y = *reinterpret_cast<float4*>(&g_Y[base + fi]);
            y.x += acc[fi + 0][hh];
            y.y += acc[fi + 1][hh];
            y.z += acc[fi + 2][hh];
            y.w += acc[fi + 3][hh];
            *reinterpret_cast<float4*>(&g_Y[base + fi]) = y;
        }
    }
}

// ---------------------------------------------------------------------------
extern "C" void kernel_launch(void* const* d_in, const int* in_sizes, int n_in,
                              void* d_out, int out_size) {
    (void)in_sizes; (void)n_in; (void)out_size;
    const float* act   = (const float*)d_in[0];
    const float* lns   = (const float*)d_in[1];
    const float* probs = (const float*)d_in[2];
    const float* pf    = (const float*)d_in[3];
    const float* W_O   = (const float*)d_in[4];
    const float* W_V   = (const float*)d_in[5];
    const float* W_enc = (const float*)d_in[6];
    const float* b_enc = (const float*)d_in[7];
    const float* b_dec = (const float*)d_in[8];
    const float* W_dec = (const float*)d_in[9];
    const float* upb   = (const float*)d_in[10];
    const unsigned char* mask = (const unsigned char*)d_in[11];
    float* out = (float*)d_out;

    float *WOV, *A1, *xln, *Y;
    cudaGetSymbolAddress((void**)&WOV, g_WOV);
    cudaGetSymbolAddress((void**)&A1,  g_A1);
    cudaGetSymbolAddress((void**)&xln, g_xln);
    cudaGetSymbolAddress((void**)&Y,   g_Y);

    const long DD = (long)D_ * D_;
    const long FD = (long)F_ * D_;
    const long SF = (long)S_ * F_;
    const long SD = (long)S_ * D_;
    const long SS = (long)S_ * S_;

    detect_mask_k<<<1, 32>>>(mask);

    // mask CSR structure (depends only on mask + mode)
    count_k<<<(F_ * 32 + 255) / 256, 256>>>(mask);
    scan_k<<<1, 256>>>();
    fill_k<<<(F_ * 32 + 255) / 256, 256>>>(mask);

    // elementwise prep
    {
        long tot = (long)B_ * S_ * D_;
        prep_x_k<<<(int)((tot + 255) / 256), 256>>>(act, lns);
    }
    prep_upT_k<<<dim3(F_ / 32, BS_ / 32), dim3(32, 8)>>>(pf, lns);

    // 1) W_OV[h] = W_V[h] @ W_O[h]   NN
    sgemm_k<0, 0, 0><<<dim3(D_ / BN, D_ / BM, H_), 256>>>(
        W_V, W_O, WOV, DH_, DH_, D_, D_, H_,
        0, (long)D_ * DH_, 0, (long)DH_ * D_, 0, DD);

    // bias vectors
    c_k<<<dim3(3, H_, 8), 256>>>(upb);
    bias_vec_k<<<F_ / 256, 256>>>(W_enc, b_enc, b_dec);

    // 3) A1[h] = W_enc (2048x768) @ W_OV[h]^T   NT   (== M1^T, reused for 5a)
    sgemm_k<0, 1, 0><<<dim3(D_ / BN, F_ / BM, H_), 256>>>(
        W_enc, WOV, A1, D_, D_, D_, D_, H_,
        0, 0, 0, DD, 0, FD);

    // 4) vw[h] = (A1[h] @ W_dec) * mask  -> compact scatter into g_vwval
    sgemm_k<0, 0, 2><<<dim3(F_ / BN, F_ / BM, H_), 256>>>(
        A1, W_dec, xln /*unused*/, D_, D_, F_, F_, H_,
        0, FD, 0, 0, 0, 0);

    // 5a) Y[b,h] = x_ln[b] (512x768) @ A1[h]^T (768x2048)   NT, init
    sgemm_k<0, 1, 0><<<dim3(F_ / BN, S_ / BM, B_ * H_), 256>>>(
        xln, A1, Y, D_, D_, D_, F_, H_,
        SD, 0, 0, FD, (long)H_ * SF, SF);

    // 5b) Y[b,h,k,f] += sum over masked g of up_lnT[g,bk] * vwval[h, slot(f,g)]
    spmm_k<<<dim3(BS_ / 256, F_ / FT, H_ / HT), 256>>>();

    // 6) out[b] = sum_h probs[b,h] @ Y[b,h]   (K = H*S = 6144)
    sgemm_k<1, 0, 0><<<dim3(F_ / BN, S_ / BM, B_), 256>>>(
        probs, Y, out, H_ * S_, S_, F_, F_, 1,
        (long)H_ * SS, 0, (long)H_ * SF, 0, SF, 0);

    // 7) out += bias0[f] + e[f] / ln_scale
    {
        long tot = (long)B_ * S_ * F_;
        finish_k<<<(int)((tot + 255) / 256), 256>>>(out, lns);
    }
}

// round 5
// speedup vs baseline: 3.2544x; 2.2900x over previous
#include <cuda_runtime.h>

// Problem constants
#define B_  4
#define S_  512
#define D_  768
#define H_  12
#define DH_ 64
#define F_  2048
#define BS_ (B_ * S_)          // 2048
#define HK_ (H_ * S_)          // 6144
#define NNZCAP 262144          // cap on mask nonzeros (expected ~210K)

// ---------------- scratch (device globals; no allocations allowed) ----------
__device__ float g_WOV  [H_ * D_ * D_];      // [h][m][o]
__device__ float g_A1   [H_ * F_ * D_];      // [h][f][m] = W_enc @ W_OV[h]^T
__device__ float g_WdecT[F_ * D_];           // [g][m]
__device__ float g_xln  [B_ * S_ * D_];
__device__ float g_uplnT[F_ * BS_];          // [g][bk]
__device__ float g_Yt   [B_ * F_ * HK_];     // [b][f][h*S+k]
__device__ float g_vwval[H_ * NNZCAP];
__device__ int   g_slot [(long)F_ * F_];     // (f,g) -> compact index or -1
__device__ int   g_gidx [NNZCAP];
__device__ int   g_cnt  [F_];
__device__ int   g_rowptr[F_ + 1];
__device__ float g_c    [D_];
__device__ float g_bias0[F_];
__device__ float g_e    [F_];
__device__ int   g_maskmode;

// ---------------- mask dtype detector ---------------------------------------
__global__ void detect_mask_k(const unsigned char* __restrict__ m) {
    if (threadIdx.x != 0 || blockIdx.x != 0) return;
    int sawF = 0, sawB = 0;
    for (int i = 0; i < 65536; i++) {
        unsigned char v = m[i];
        if (v == 63 || v == 128) sawF = 1;
        else if (v != 0 && (i & 3) != 0) sawB = 1;
    }
    g_maskmode = sawF ? 2 : (sawB ? 0 : 1);
}

__device__ __forceinline__ int mask_nz(const unsigned char* m, long idx, int mode) {
    if (mode == 0) return m[idx] != 0;
    if (mode == 1) return ((const int*)m)[idx] != 0;
    return ((const float*)m)[idx] != 0.f;
}

// ---------------- mask CSR builders -----------------------------------------
__global__ void count_k(const unsigned char* __restrict__ m) {
    int w = (blockIdx.x * blockDim.x + threadIdx.x) >> 5;
    int lane = threadIdx.x & 31;
    if (w >= F_) return;
    int mode = g_maskmode;
    int cnt = 0;
    for (int g0 = 0; g0 < F_; g0 += 32) {
        int v = mask_nz(m, (long)w * F_ + g0 + lane, mode);
        cnt += __popc(__ballot_sync(0xffffffffu, v));
    }
    if (lane == 0) g_cnt[w] = cnt;
}

__global__ void scan_k() {
    __shared__ int part[256];
    int t = threadIdx.x;
    int base = t * 8;
    int s = 0;
    for (int i = 0; i < 8; i++) s += g_cnt[base + i];
    part[t] = s;
    __syncthreads();
    if (t == 0) {
        int r = 0;
        for (int i = 0; i < 256; i++) { int v = part[i]; part[i] = r; r += v; }
        g_rowptr[F_] = r;
    }
    __syncthreads();
    int r = part[t];
    for (int i = 0; i < 8; i++) { g_rowptr[base + i] = r; r += g_cnt[base + i]; }
}

__global__ void fill_k(const unsigned char* __restrict__ m) {
    int w = (blockIdx.x * blockDim.x + threadIdx.x) >> 5;
    int lane = threadIdx.x & 31;
    if (w >= F_) return;
    int mode = g_maskmode;
    int base = g_rowptr[w];
    unsigned lt = (1u << lane) - 1u;
    for (int g0 = 0; g0 < F_; g0 += 32) {
        int g = g0 + lane;
        int v = mask_nz(m, (long)w * F_ + g, mode);
        unsigned bal = __ballot_sync(0xffffffffu, v);
        int pos = base + __popc(bal & lt);
        int slot = (v && pos < NNZCAP) ? pos : -1;
        g_slot[(long)w * F_ + g] = slot;
        if (slot >= 0) g_gidx[slot] = g;
        base += __popc(bal);
    }
}

// ---------------- elementwise prep ------------------------------------------
__global__ void prep_x_k(const float* __restrict__ act, const float* __restrict__ lns) {
    long i = (long)blockIdx.x * blockDim.x + threadIdx.x;
    if (i < (long)B_ * S_ * D_) g_xln[i] = act[i] / lns[i / D_];
    if (i < D_) g_c[i] = 0.f;
}

__global__ void prep_upT_k(const float* __restrict__ pf, const float* __restrict__ lns) {
    __shared__ float tile[32][33];
    int tx = threadIdx.x, ty = threadIdx.y;
    int g = blockIdx.x * 32 + tx;
    int bk0 = blockIdx.y * 32;
    #pragma unroll
    for (int i = 0; i < 32; i += 8) {
        int bk = bk0 + ty + i;
        tile[ty + i][tx] = pf[(long)bk * F_ + g] / lns[bk];
    }
    __syncthreads();
    int bkOut = bk0 + tx;
    #pragma unroll
    for (int i = 0; i < 32; i += 8)
        g_uplnT[(long)(blockIdx.x * 32 + ty + i) * BS_ + bkOut] = tile[tx][ty + i];
}

// W_decT[g][m] = W_dec[m][g]
__global__ void tpose_wdec_k(const float* __restrict__ wd) {
    __shared__ float tile[32][33];
    int tx = threadIdx.x, ty = threadIdx.y;
    int g = blockIdx.x * 32 + tx;
    int m0 = blockIdx.y * 32;
    #pragma unroll
    for (int i = 0; i < 32; i += 8)
        tile[ty + i][tx] = wd[(long)(m0 + ty + i) * F_ + g];
    __syncthreads();
    int mOut = m0 + tx;
    #pragma unroll
    for (int i = 0; i < 32; i += 8)
        g_WdecT[(long)(blockIdx.x * 32 + ty + i) * D_ + mOut] = tile[tx][ty + i];
}

// ---------------- bias vectors ----------------------------------------------
__global__ void c_k(const float* __restrict__ upb) {
    int d = blockIdx.x * 256 + threadIdx.x;
    int h = blockIdx.y;
    int m0 = blockIdx.z * 96;
    if (d >= D_) return;
    const float* base = g_WOV + (long)h * D_ * D_;
    float s = 0.f;
    for (int m = m0; m < m0 + 96; m++) s += base[(long)m * D_ + d] * upb[m];
    atomicAdd(&g_c[d], s);
}

__global__ void bias_vec_k(const float* __restrict__ W_enc,
                           const float* __restrict__ b_enc,
                           const float* __restrict__ b_dec) {
    int f = blockIdx.x * 256 + threadIdx.x;
    if (f >= F_) return;
    const float* row = W_enc + (long)f * D_;
    float s0 = 0.f, s1 = 0.f;
    for (int d = 0; d < D_; d++) {
        float w = row[d];
        s0 += w * b_dec[d];
        s1 += w * g_c[d];
    }
    g_bias0[f] = b_enc[f] - s0;
    g_e[f] = s1;
}

__global__ void finish_k(float* __restrict__ out, const float* __restrict__ lns) {
    long i = (long)blockIdx.x * blockDim.x + threadIdx.x;
    if (i >= (long)B_ * S_ * F_) return;
    int f = (int)(i & (F_ - 1));
    long row = i >> 11;
    out[i] += g_bias0[f] + g_e[f] / lns[row];
}

// ---------------- FFMA SGEMM (step 1 only: small) ----------------------------
constexpr int BM = 128, BN = 128, BKK = 8, TM = 8, TN = 8;

__global__ __launch_bounds__(256)
void sgemm_nn_k(const float* __restrict__ A, const float* __restrict__ B,
                float* __restrict__ C, int K, int lda, int ldb, int ldc,
                long sAh, long sBh, long sCh) {
    const int zh = blockIdx.z;
    A += zh * sAh; B += zh * sBh; C += zh * sCh;

    __shared__ float As[BKK][BM + 4];
    __shared__ float Bs[BKK][BN + 4];

    const int tid = threadIdx.x;
    const int tx = tid & 15, ty = tid >> 4;
    const int row0 = blockIdx.y * BM, col0 = blockIdx.x * BN;
    const int aRow = tid >> 1, aCol = (tid & 1) << 2;
    const int bR = tid >> 5, bC = (tid & 31) << 2;

    float acc[TM][TN];
    #pragma unroll
    for (int i = 0; i < TM; i++)
        #pragma unroll
        for (int j = 0; j < TN; j++) acc[i][j] = 0.f;

    for (int k0 = 0; k0 < K; k0 += BKK) {
        float4 av = *reinterpret_cast<const float4*>(A + (long)(row0 + aRow) * lda + k0 + aCol);
        As[aCol + 0][aRow] = av.x; As[aCol + 1][aRow] = av.y;
        As[aCol + 2][aRow] = av.z; As[aCol + 3][aRow] = av.w;
        float4 bv = *reinterpret_cast<const float4*>(B + (long)(k0 + bR) * ldb + col0 + bC);
        *reinterpret_cast<float4*>(&Bs[bR][bC]) = bv;
        __syncthreads();
        #pragma unroll
        for (int kk = 0; kk < BKK; kk++) {
            float a[TM], bb[TN];
            #pragma unroll
            for (int i = 0; i < TM; i++) a[i] = As[kk][ty * TM + i];
            #pragma unroll
            for (int j = 0; j < TN; j++) bb[j] = Bs[kk][tx * TN + j];
            #pragma unroll
            for (int i = 0; i < TM; i++)
                #pragma unroll
                for (int j = 0; j < TN; j++) acc[i][j] += a[i] * bb[j];
        }
        __syncthreads();
    }
    #pragma unroll
    for (int i = 0; i < TM; i++) {
        long r = row0 + ty * TM + i;
        #pragma unroll
        for (int j = 0; j < TN; j++)
            C[r * ldc + col0 + tx * TN + j] = acc[i][j];
    }
}

// ================ tf32 mma.sync GEMM (NT: C[M,N] = A[M,K]*B[N,K]^T) ==========
// Block 128x128, K-chunk 32. 8 warps in 2(M)x4(N); warp tile 64x32.
// mma.sync.aligned.m16n8k8.row.col.f32.tf32.tf32.f32 (sm_80+ PTX; no 'a' gate).
// Shared [128][36] (pad 4): fragment LDS addr = r*36+c == lane mod 32 -> conflict-free.
// Values tf32-rounded (cvt.rna) at STS time.
// AMODE 0: A row-major [M,K] lda.  AMODE 1: A = probs[b] piecewise over heads.
// OUTM 0: C = acc (ldc).           OUTM 2: masked scatter to g_vwval via g_slot.
#define MK 32
#define PAD 36

__device__ __forceinline__ unsigned f2tf32(float x) {
    unsigned r;
    asm("cvt.rna.tf32.f32 %0, %1;" : "=r"(r) : "f"(x));
    return r;
}

template<int AMODE, int OUTM>
__global__ __launch_bounds__(256)
void mma_k(const float* __restrict__ Ag, const float* __restrict__ Bg,
           float* __restrict__ Cg,
           int K, int lda, int ldb, int ldc, int Hdim,
           long sAb, long sAh, long sBb, long sBh, long sCb, long sCh) {
    __shared__ float As[128][PAD];
    __shared__ float Bs[128][PAD];

    const int zb = blockIdx.z / Hdim, zh = blockIdx.z % Hdim;
    const float* A = Ag + zb * sAb + zh * sAh;
    const float* B = Bg + zb * sBb + zh * sBh;
    float* C = Cg + zb * sCb + zh * sCh;

    const int row0 = blockIdx.y * 128, col0 = blockIdx.x * 128;
    const int tid = threadIdx.x, wid = tid >> 5, lane = tid & 31;
    const int warpM = (wid & 1) * 64, warpN = (wid >> 1) * 32;
    const int lr = lane >> 2, lc = lane & 3;

    float acc[4][4][4];
    #pragma unroll
    for (int im = 0; im < 4; im++)
        #pragma unroll
        for (int in = 0; in < 4; in++)
            #pragma unroll
            for (int q = 0; q < 4; q++) acc[im][in][q] = 0.f;

    const int sr = tid >> 3, sc = (tid & 7) * 4;   // staging row / col(4-float)
    const int nch = K / MK;
    float4 na[4], nb[4];

    // ---- load chunk c into regs ----
    auto ldg = [&](int c) {
        const int k0 = c * MK;
        #pragma unroll
        for (int i = 0; i < 4; i++) {
            int r = sr + i * 32;
            const float* srcA;
            if (AMODE == 0) srcA = A + (long)(row0 + r) * lda + k0 + sc;
            else {
                int kk = k0 + sc;
                srcA = A + (long)(kk >> 9) * (S_ * S_) + (long)(row0 + r) * S_ + (kk & (S_ - 1));
            }
            na[i] = *reinterpret_cast<const float4*>(srcA);
            nb[i] = *reinterpret_cast<const float4*>(B + (long)(col0 + r) * ldb + k0 + sc);
        }
    };
    // ---- cvt + store regs to smem ----
    auto sts = [&]() {
        #pragma unroll
        for (int i = 0; i < 4; i++) {
            int r = sr + i * 32;
            As[r][sc + 0] = __uint_as_float(f2tf32(na[i].x));
            As[r][sc + 1] = __uint_as_float(f2tf32(na[i].y));
            As[r][sc + 2] = __uint_as_float(f2tf32(na[i].z));
            As[r][sc + 3] = __uint_as_float(f2tf32(na[i].w));
            Bs[r][sc + 0] = __uint_as_float(f2tf32(nb[i].x));
            Bs[r][sc + 1] = __uint_as_float(f2tf32(nb[i].y));
            Bs[r][sc + 2] = __uint_as_float(f2tf32(nb[i].z));
            Bs[r][sc + 3] = __uint_as_float(f2tf32(nb[i].w));
        }
    };

    ldg(0);
    sts();
    __syncthreads();

    for (int c = 0; c < nch; c++) {
        if (c + 1 < nch) ldg(c + 1);
        #pragma unroll
        for (int ks = 0; ks < 4; ks++) {
            const int kc = ks * 8 + lc;
            unsigned af[4][4], bf[4][2];
            #pragma unroll
            for (int im = 0; im < 4; im++) {
                int r = warpM + im * 16 + lr;
                af[im][0] = __float_as_uint(As[r][kc]);
                af[im][1] = __float_as_uint(As[r + 8][kc]);
                af[im][2] = __float_as_uint(As[r][kc + 4]);
                af[im][3] = __float_as_uint(As[r + 8][kc + 4]);
            }
            #pragma unroll
            for (int in = 0; in < 4; in++) {
                int r = warpN + in * 8 + lr;
                bf[in][0] = __float_as_uint(Bs[r][kc]);
                bf[in][1] = __float_as_uint(Bs[r][kc + 4]);
            }
            #pragma unroll
            for (int im = 0; im < 4; im++)
                #pragma unroll
                for (int in = 0; in < 4; in++) {
                    asm volatile(
                        "mma.sync.aligned.m16n8k8.row.col.f32.tf32.tf32.f32 "
                        "{%0,%1,%2,%3}, {%4,%5,%6,%7}, {%8,%9}, {%0,%1,%2,%3};"
                        : "+f"(acc[im][in][0]), "+f"(acc[im][in][1]),
                          "+f"(acc[im][in][2]), "+f"(acc[im][in][3])
                        : "r"(af[im][0]), "r"(af[im][1]), "r"(af[im][2]), "r"(af[im][3]),
                          "r"(bf[in][0]), "r"(bf[in][1]));
                }
        }
        __syncthreads();
        if (c + 1 < nch) {
            sts();
            __syncthreads();
        }
    }

    // epilogue: c0,c1 at (r, cc..cc+1); c2,c3 at (r+8, cc..cc+1)
    #pragma unroll
    for (int im = 0; im < 4; im++) {
        int r = row0 + warpM + im * 16 + lr;
        #pragma unroll
        for (int in = 0; in < 4; in++) {
            int cc = col0 + warpN + in * 8 + lc * 2;
            if (OUTM == 0) {
                *reinterpret_cast<float2*>(C + (long)r * ldc + cc) =
                    make_float2(acc[im][in][0], acc[im][in][1]);
                *reinterpret_cast<float2*>(C + (long)(r + 8) * ldc + cc) =
                    make_float2(acc[im][in][2], acc[im][in][3]);
            } else {
                int s0 = g_slot[(long)r * F_ + cc];
                int s1 = g_slot[(long)r * F_ + cc + 1];
                int s2 = g_slot[(long)(r + 8) * F_ + cc];
                int s3 = g_slot[(long)(r + 8) * F_ + cc + 1];
                if (s0 >= 0) g_vwval[(long)zh * NNZCAP + s0] = acc[im][in][0];
                if (s1 >= 0) g_vwval[(long)zh * NNZCAP + s1] = acc[im][in][1];
                if (s2 >= 0) g_vwval[(long)zh * NNZCAP + s2] = acc[im][in][2];
                if (s3 >= 0) g_vwval[(long)zh * NNZCAP + s3] = acc[im][in][3];
            }
        }
    }
}

// ---------------- spMM: Yt[b,f,h*S+k] += sum_j uplnT[gidx[j],bk]*vwval[h,j] --
constexpr int FT2 = 8;

__global__ __launch_bounds__(256)
void spmm_k() {
    const int t = threadIdx.x;
    const int bk = blockIdx.x * 256 + t;
    const int f0 = blockIdx.y * FT2;

    float acc[FT2][H_];
    #pragma unroll
    for (int i = 0; i < FT2; i++)
        #pragma unroll
        for (int h = 0; h < H_; h++) acc[i][h] = 0.f;

    #pragma unroll 1
    for (int fi = 0; fi < FT2; fi++) {
        const int f = f0 + fi;
        int j = g_rowptr[f];
        const int je = g_rowptr[f + 1];
        for (; j + 1 < je; j += 2) {
            int   ga = g_gidx[j], gb = g_gidx[j + 1];
            float xa = g_uplnT[(long)ga * BS_ + bk];
            float xb = g_uplnT[(long)gb * BS_ + bk];
            #pragma unroll
            for (int h = 0; h < H_; h++) {
                const float* vp = g_vwval + (long)h * NNZCAP + j;
                acc[fi][h] += xa * vp[0];
                acc[fi][h] += xb * vp[1];
            }
        }
        for (; j < je; j++) {
            int g = g_gidx[j];
            float x = g_uplnT[(long)g * BS_ + bk];
            #pragma unroll
            for (int h = 0; h < H_; h++)
                acc[fi][h] += x * g_vwval[(long)h * NNZCAP + j];
        }
    }

    const int b = bk >> 9, k = bk & (S_ - 1);
    #pragma unroll 1
    for (int fi = 0; fi < FT2; fi++) {
        long base = ((long)b * F_ + f0 + fi) * HK_ + k;
        #pragma unroll
        for (int h = 0; h < H_; h++)
            g_Yt[base + h * S_] += acc[fi][h];
    }
}

// ---------------------------------------------------------------------------
extern "C" void kernel_launch(void* const* d_in, const int* in_sizes, int n_in,
                              void* d_out, int out_size) {
    (void)in_sizes; (void)n_in; (void)out_size;
    const float* act   = (const float*)d_in[0];
    const float* lns   = (const float*)d_in[1];
    const float* probs = (const float*)d_in[2];
    const float* pf    = (const float*)d_in[3];
    const float* W_O   = (const float*)d_in[4];
    const float* W_V   = (const float*)d_in[5];
    const float* W_enc = (const float*)d_in[6];
    const float* b_enc = (const float*)d_in[7];
    const float* b_dec = (const float*)d_in[8];
    const float* W_dec = (const float*)d_in[9];
    const float* upb   = (const float*)d_in[10];
    const unsigned char* mask = (const unsigned char*)d_in[11];
    float* out = (float*)d_out;

    float *WOV, *A1, *WdT, *xln, *Yt;
    cudaGetSymbolAddress((void**)&WOV, g_WOV);
    cudaGetSymbolAddress((void**)&A1,  g_A1);
    cudaGetSymbolAddress((void**)&WdT, g_WdecT);
    cudaGetSymbolAddress((void**)&xln, g_xln);
    cudaGetSymbolAddress((void**)&Yt,  g_Yt);

    const long DD = (long)D_ * D_;
    const long FD = (long)F_ * D_;
    const long SD = (long)S_ * D_;
    const long SS = (long)S_ * S_;
    const long FHK = (long)F_ * HK_;

    detect_mask_k<<<1, 32>>>(mask);
    count_k<<<(F_ * 32 + 255) / 256, 256>>>(mask);
    scan_k<<<1, 256>>>();
    fill_k<<<(F_ * 32 + 255) / 256, 256>>>(mask);

    {
        long tot = (long)B_ * S_ * D_;
        prep_x_k<<<(int)((tot + 255) / 256), 256>>>(act, lns);
    }
    prep_upT_k<<<dim3(F_ / 32, BS_ / 32), dim3(32, 8)>>>(pf, lns);
    tpose_wdec_k<<<dim3(F_ / 32, D_ / 32), dim3(32, 8)>>>(W_dec);

    // 1) W_OV[h] = W_V[h] @ W_O[h]   (FFMA, small)
    sgemm_nn_k<<<dim3(D_ / BN, D_ / BM, H_), 256>>>(
        W_V, W_O, WOV, DH_, DH_, D_, D_,
        (long)D_ * DH_, (long)DH_ * D_, DD);

    c_k<<<dim3(3, H_, 8), 256>>>(upb);
    bias_vec_k<<<F_ / 256, 256>>>(W_enc, b_enc, b_dec);

    // 3) A1[h][f][m] = W_enc[f,:] . W_OV[h][m,:]   M=2048 N=768 K=768
    mma_k<0, 0><<<dim3(D_ / 128, F_ / 128, H_), 256>>>(
        W_enc, WOV, A1, D_, D_, D_, D_, H_,
        0, 0, 0, DD, 0, FD);

    // 4) vw[h][f][g] = A1[h][f,:] . WdecT[g,:] -> masked scatter  M=2048 N=2048 K=768
    mma_k<0, 2><<<dim3(F_ / 128, F_ / 128, H_), 256>>>(
        A1, WdT, xln /*unused*/, D_, D_, D_, 0, H_,
        0, FD, 0, 0, 0, 0);

    // 5a) Yt[b][f][h*S+k] = A1[h][f,:] . xln[b][k,:]   M=2048 N=512 K=768
    mma_k<0, 0><<<dim3(S_ / 128, F_ / 128, B_ * H_), 256>>>(
        A1, xln, Yt, D_, D_, D_, HK_, H_,
        0, FD, SD, 0, FHK, (long)S_);

    // 5b) sparse accumulate into Yt
    spmm_k<<<dim3(BS_ / 256, F_ / FT2), 256>>>();

    // 6) out[b][q][f] = probs[b][q,:(hk)] . Yt[b][f,:(hk)]   M=512 N=2048 K=6144
    mma_k<1, 0><<<dim3(F_ / 128, S_ / 128, B_), 256>>>(
        probs, Yt, out, HK_, 0, HK_, F_, 1,
        (long)H_ * SS, 0, FHK, 0, (long)S_ * F_, 0);

    // 7) out += bias0[f] + e[f] / ln_scale
    {
        long tot = (long)B_ * S_ * F_;
        finish_k<<<(int)((tot + 255) / 256), 256>>>(out, lns);
    }
}

// round 6
// speedup vs baseline: 3.7277x; 1.1454x over previous
#include <cuda_runtime.h>

// Problem constants
#define B_  4
#define S_  512
#define D_  768
#define H_  12
#define DH_ 64
#define F_  2048
#define BS_ (B_ * S_)          // 2048
#define HK_ (H_ * S_)          // 6144
#define NNZCAP 262144          // cap on mask nonzeros (expected ~210K)

// ---------------- scratch (device globals; no allocations allowed) ----------
__device__ float g_WOV  [H_ * D_ * D_];      // [h][m][o]   tf32-rounded
__device__ float g_A1   [H_ * F_ * D_];      // [h][f][m]   tf32-rounded
__device__ float g_WdecT[F_ * D_];           // [g][m]      tf32-rounded
__device__ float g_WencR[F_ * D_];           // rounded copy of W_enc
__device__ float g_xln  [B_ * S_ * D_];      // tf32-rounded
__device__ float g_probsR[B_ * H_ * S_ * S_];// rounded copy of probs
__device__ float g_uplnT[F_ * BS_];          // [g][bk] fp32
__device__ float g_Yt   [B_ * F_ * HK_];     // [b][f][h*S+k] tf32-rounded
__device__ float g_vwval[H_ * NNZCAP];       // fp32
__device__ int   g_slot [(long)F_ * F_];
__device__ int   g_gidx [NNZCAP];
__device__ int   g_cnt  [F_];
__device__ int   g_rowptr[F_ + 1];
__device__ float g_c    [D_];
__device__ float g_bias0[F_];
__device__ float g_e    [F_];
__device__ int   g_maskmode;

__device__ __forceinline__ unsigned f2tf32(float x) {
    unsigned r;
    asm("cvt.rna.tf32.f32 %0, %1;" : "=r"(r) : "f"(x));
    return r;
}
__device__ __forceinline__ float rnd(float x) { return __uint_as_float(f2tf32(x)); }

// ---------------- mask dtype detector ---------------------------------------
__global__ void detect_mask_k(const unsigned char* __restrict__ m) {
    if (threadIdx.x != 0 || blockIdx.x != 0) return;
    int sawF = 0, sawB = 0;
    for (int i = 0; i < 65536; i++) {
        unsigned char v = m[i];
        if (v == 63 || v == 128) sawF = 1;
        else if (v != 0 && (i & 3) != 0) sawB = 1;
    }
    g_maskmode = sawF ? 2 : (sawB ? 0 : 1);
}

__device__ __forceinline__ int mask_nz(const unsigned char* m, long idx, int mode) {
    if (mode == 0) return m[idx] != 0;
    if (mode == 1) return ((const int*)m)[idx] != 0;
    return ((const float*)m)[idx] != 0.f;
}

// ---------------- mask CSR builders -----------------------------------------
__global__ void count_k(const unsigned char* __restrict__ m) {
    int w = (blockIdx.x * blockDim.x + threadIdx.x) >> 5;
    int lane = threadIdx.x & 31;
    if (w >= F_) return;
    int mode = g_maskmode;
    int cnt = 0;
    for (int g0 = 0; g0 < F_; g0 += 32) {
        int v = mask_nz(m, (long)w * F_ + g0 + lane, mode);
        cnt += __popc(__ballot_sync(0xffffffffu, v));
    }
    if (lane == 0) g_cnt[w] = cnt;
}

__global__ void scan_k() {
    __shared__ int part[256];
    int t = threadIdx.x;
    int base = t * 8;
    int s = 0;
    for (int i = 0; i < 8; i++) s += g_cnt[base + i];
    part[t] = s;
    __syncthreads();
    if (t == 0) {
        int r = 0;
        for (int i = 0; i < 256; i++) { int v = part[i]; part[i] = r; r += v; }
        g_rowptr[F_] = r;
    }
    __syncthreads();
    int r = part[t];
    for (int i = 0; i < 8; i++) { g_rowptr[base + i] = r; r += g_cnt[base + i]; }
}

__global__ void fill_k(const unsigned char* __restrict__ m) {
    int w = (blockIdx.x * blockDim.x + threadIdx.x) >> 5;
    int lane = threadIdx.x & 31;
    if (w >= F_) return;
    int mode = g_maskmode;
    int base = g_rowptr[w];
    unsigned lt = (1u << lane) - 1u;
    for (int g0 = 0; g0 < F_; g0 += 32) {
        int g = g0 + lane;
        int v = mask_nz(m, (long)w * F_ + g, mode);
        unsigned bal = __ballot_sync(0xffffffffu, v);
        int pos = base + __popc(bal & lt);
        int slot = (v && pos < NNZCAP) ? pos : -1;
        g_slot[(long)w * F_ + g] = slot;
        if (slot >= 0) g_gidx[slot] = g;
        base += __popc(bal);
    }
}

// ---------------- elementwise prep ------------------------------------------
__global__ void prep_x_k(const float* __restrict__ act, const float* __restrict__ lns) {
    long i = (long)blockIdx.x * blockDim.x + threadIdx.x;
    if (i < (long)B_ * S_ * D_) g_xln[i] = rnd(act[i] / lns[i / D_]);
    if (i < D_) g_c[i] = 0.f;
}

// rounded copies of W_enc and probs (tf32 operands must be pre-rounded)
__global__ void round_wenc_k(const float* __restrict__ w) {
    long i = (long)blockIdx.x * blockDim.x + threadIdx.x;
    if (i < (long)F_ * D_) g_WencR[i] = rnd(w[i]);
}
__global__ void round_probs_k(const float* __restrict__ p) {
    long i = (long)blockIdx.x * blockDim.x + threadIdx.x;
    long tot = (long)B_ * H_ * S_ * S_;
    if (i < tot) g_probsR[i] = rnd(p[i]);
}

__global__ void prep_upT_k(const float* __restrict__ pf, const float* __restrict__ lns) {
    __shared__ float tile[32][33];
    int tx = threadIdx.x, ty = threadIdx.y;
    int g = blockIdx.x * 32 + tx;
    int bk0 = blockIdx.y * 32;
    #pragma unroll
    for (int i = 0; i < 32; i += 8) {
        int bk = bk0 + ty + i;
        tile[ty + i][tx] = pf[(long)bk * F_ + g] / lns[bk];
    }
    __syncthreads();
    int bkOut = bk0 + tx;
    #pragma unroll
    for (int i = 0; i < 32; i += 8)
        g_uplnT[(long)(blockIdx.x * 32 + ty + i) * BS_ + bkOut] = tile[tx][ty + i];
}

// W_decT[g][m] = W_dec[m][g]   (rounded)
__global__ void tpose_wdec_k(const float* __restrict__ wd) {
    __shared__ float tile[32][33];
    int tx = threadIdx.x, ty = threadIdx.y;
    int g = blockIdx.x * 32 + tx;
    int m0 = blockIdx.y * 32;
    #pragma unroll
    for (int i = 0; i < 32; i += 8)
        tile[ty + i][tx] = wd[(long)(m0 + ty + i) * F_ + g];
    __syncthreads();
    int mOut = m0 + tx;
    #pragma unroll
    for (int i = 0; i < 32; i += 8)
        g_WdecT[(long)(blockIdx.x * 32 + ty + i) * D_ + mOut] = rnd(tile[tx][ty + i]);
}

// ---------------- bias vectors ----------------------------------------------
__global__ void c_k(const float* __restrict__ upb) {
    int d = blockIdx.x * 256 + threadIdx.x;
    int h = blockIdx.y;
    int m0 = blockIdx.z * 96;
    if (d >= D_) return;
    const float* base = g_WOV + (long)h * D_ * D_;
    float s = 0.f;
    for (int m = m0; m < m0 + 96; m++) s += base[(long)m * D_ + d] * upb[m];
    atomicAdd(&g_c[d], s);
}

__global__ void bias_vec_k(const float* __restrict__ W_enc,
                           const float* __restrict__ b_enc,
                           const float* __restrict__ b_dec) {
    int f = blockIdx.x * 256 + threadIdx.x;
    if (f >= F_) return;
    const float* row = W_enc + (long)f * D_;
    float s0 = 0.f, s1 = 0.f;
    for (int d = 0; d < D_; d++) {
        float w = row[d];
        s0 += w * b_dec[d];
        s1 += w * g_c[d];
    }
    g_bias0[f] = b_enc[f] - s0;
    g_e[f] = s1;
}

__global__ void finish_k(float* __restrict__ out, const float* __restrict__ lns) {
    long i = (long)blockIdx.x * blockDim.x + threadIdx.x;
    if (i >= (long)B_ * S_ * F_) return;
    int f = (int)(i & (F_ - 1));
    long row = i >> 11;
    out[i] += g_bias0[f] + g_e[f] / lns[row];
}

// ---------------- FFMA SGEMM (step 1 only: small) ----------------------------
constexpr int BM = 128, BN = 128, BKK = 8, TM = 8, TN = 8;

__global__ __launch_bounds__(256)
void sgemm_nn_k(const float* __restrict__ A, const float* __restrict__ B,
                float* __restrict__ C, int K, int lda, int ldb, int ldc,
                long sAh, long sBh, long sCh) {
    const int zh = blockIdx.z;
    A += zh * sAh; B += zh * sBh; C += zh * sCh;

    __shared__ float As[BKK][BM + 4];
    __shared__ float Bs[BKK][BN + 4];

    const int tid = threadIdx.x;
    const int tx = tid & 15, ty = tid >> 4;
    const int row0 = blockIdx.y * BM, col0 = blockIdx.x * BN;
    const int aRow = tid >> 1, aCol = (tid & 1) << 2;
    const int bR = tid >> 5, bC = (tid & 31) << 2;

    float acc[TM][TN];
    #pragma unroll
    for (int i = 0; i < TM; i++)
        #pragma unroll
        for (int j = 0; j < TN; j++) acc[i][j] = 0.f;

    for (int k0 = 0; k0 < K; k0 += BKK) {
        float4 av = *reinterpret_cast<const float4*>(A + (long)(row0 + aRow) * lda + k0 + aCol);
        As[aCol + 0][aRow] = av.x; As[aCol + 1][aRow] = av.y;
        As[aCol + 2][aRow] = av.z; As[aCol + 3][aRow] = av.w;
        float4 bv = *reinterpret_cast<const float4*>(B + (long)(k0 + bR) * ldb + col0 + bC);
        *reinterpret_cast<float4*>(&Bs[bR][bC]) = bv;
        __syncthreads();
        #pragma unroll
        for (int kk = 0; kk < BKK; kk++) {
            float a[TM], bb[TN];
            #pragma unroll
            for (int i = 0; i < TM; i++) a[i] = As[kk][ty * TM + i];
            #pragma unroll
            for (int j = 0; j < TN; j++) bb[j] = Bs[kk][tx * TN + j];
            #pragma unroll
            for (int i = 0; i < TM; i++)
                #pragma unroll
                for (int j = 0; j < TN; j++) acc[i][j] += a[i] * bb[j];
        }
        __syncthreads();
    }
    #pragma unroll
    for (int i = 0; i < TM; i++) {
        long r = row0 + ty * TM + i;
        #pragma unroll
        for (int j = 0; j < TN; j++)
            C[r * ldc + col0 + tx * TN + j] = rnd(acc[i][j]);  // tf32-rounded (GEMM operand)
    }
}

// ================ tf32 mma.sync GEMM, cp.async 3-stage (NT) ==================
// C[M,N] = A[M,K] * B[N,K]^T.  Block 128x128, K-chunk 32, 8 warps 2(M)x4(N).
// Operands MUST be tf32-pre-rounded in gmem (cp.async raw -> smem).
// AMODE 0: A row-major [M,K] lda.  AMODE 1: A = probsR[b] piecewise per head.
// OUTM 0: C = acc.  OUTM 2: masked scatter to g_vwval.  OUTR 1: round output.
#define MK   32
#define PAD  36
#define NSTG 3
#define STGF (128 * PAD)                      // floats per (A or B) stage
#define MMA_SMEM (NSTG * 2 * STGF * 4)        // 110592 bytes

__device__ __forceinline__ unsigned smem_u32(const void* p) {
    unsigned a;
    asm("{ .reg .u64 t; cvta.to.shared.u64 t, %1; cvt.u32.u64 %0, t; }" : "=r"(a) : "l"(p));
    return a;
}
__device__ __forceinline__ void cpasync16(unsigned dst, const void* src) {
    asm volatile("cp.async.cg.shared.global [%0], [%1], 16;" :: "r"(dst), "l"(src) : "memory");
}

template<int AMODE, int OUTM, int OUTR>
__global__ __launch_bounds__(256, 2)
void mma_k(const float* __restrict__ Ag, const float* __restrict__ Bg,
           float* __restrict__ Cg,
           int K, int lda, int ldb, int ldc, int Hdim,
           long sAb, long sAh, long sBb, long sBh, long sCb, long sCh) {
    extern __shared__ __align__(16) float sm[];

    const int zb = blockIdx.z / Hdim, zh = blockIdx.z % Hdim;
    const float* A = Ag + zb * sAb + zh * sAh;
    const float* B = Bg + zb * sBb + zh * sBh;
    float* C = Cg + zb * sCb + zh * sCh;

    const int row0 = blockIdx.y * 128, col0 = blockIdx.x * 128;
    const int tid = threadIdx.x, wid = tid >> 5, lane = tid & 31;
    const int warpM = (wid & 1) * 64, warpN = (wid >> 1) * 32;
    const int lr = lane >> 2, lc = lane & 3;

    float acc[4][4][4];
    #pragma unroll
    for (int im = 0; im < 4; im++)
        #pragma unroll
        for (int in = 0; in < 4; in++)
            #pragma unroll
            for (int q = 0; q < 4; q++) acc[im][in][q] = 0.f;

    const int nch = K / MK;
    const int ur = tid >> 3, uc = (tid & 7) * 4;   // 32 rows x 8 quads per pass

    auto issue = [&](int c) {
        float* stg = sm + (c % NSTG) * 2 * STGF;
        unsigned sa = smem_u32(stg);
        const int k0 = c * MK;
        #pragma unroll
        for (int i = 0; i < 4; i++) {
            int r = ur + i * 32;
            const float* srcA;
            if (AMODE == 0) srcA = A + (long)(row0 + r) * lda + k0 + uc;
            else {
                int kk = k0 + uc;
                srcA = A + (long)(kk >> 9) * (S_ * S_) + (long)(row0 + r) * S_ + (kk & (S_ - 1));
            }
            unsigned off = (unsigned)(r * PAD + uc) * 4u;
            cpasync16(sa + off, srcA);
            cpasync16(sa + (unsigned)STGF * 4u + off,
                      B + (long)(col0 + r) * ldb + k0 + uc);
        }
    };

    issue(0);
    asm volatile("cp.async.commit_group;" ::: "memory");
    issue(1);
    asm volatile("cp.async.commit_group;" ::: "memory");

    for (int c = 0; c < nch; c++) {
        asm volatile("cp.async.wait_group 1;" ::: "memory");
        __syncthreads();
        if (c + 2 < nch) issue(c + 2);
        asm volatile("cp.async.commit_group;" ::: "memory");  // one group per iter (maybe empty)

        const float* sA = sm + (c % NSTG) * 2 * STGF;
        const float* sB = sA + STGF;
        #pragma unroll
        for (int ks = 0; ks < 4; ks++) {
            const int kc = ks * 8 + lc;
            unsigned af[4][4], bf[4][2];
            #pragma unroll
            for (int im = 0; im < 4; im++) {
                int r = warpM + im * 16 + lr;
                af[im][0] = __float_as_uint(sA[r * PAD + kc]);
                af[im][1] = __float_as_uint(sA[(r + 8) * PAD + kc]);
                af[im][2] = __float_as_uint(sA[r * PAD + kc + 4]);
                af[im][3] = __float_as_uint(sA[(r + 8) * PAD + kc + 4]);
            }
            #pragma unroll
            for (int in = 0; in < 4; in++) {
                int r = warpN + in * 8 + lr;
                bf[in][0] = __float_as_uint(sB[r * PAD + kc]);
                bf[in][1] = __float_as_uint(sB[r * PAD + kc + 4]);
            }
            #pragma unroll
            for (int im = 0; im < 4; im++)
                #pragma unroll
                for (int in = 0; in < 4; in++) {
                    asm volatile(
                        "mma.sync.aligned.m16n8k8.row.col.f32.tf32.tf32.f32 "
                        "{%0,%1,%2,%3}, {%4,%5,%6,%7}, {%8,%9}, {%0,%1,%2,%3};"
                        : "+f"(acc[im][in][0]), "+f"(acc[im][in][1]),
                          "+f"(acc[im][in][2]), "+f"(acc[im][in][3])
                        : "r"(af[im][0]), "r"(af[im][1]), "r"(af[im][2]), "r"(af[im][3]),
                          "r"(bf[in][0]), "r"(bf[in][1]));
                }
        }
    }

    // epilogue: c0,c1 at (r, cc..cc+1); c2,c3 at (r+8, cc..cc+1)
    #pragma unroll
    for (int im = 0; im < 4; im++) {
        int r = row0 + warpM + im * 16 + lr;
        #pragma unroll
        for (int in = 0; in < 4; in++) {
            int cc = col0 + warpN + in * 8 + lc * 2;
            float v0 = acc[im][in][0], v1 = acc[im][in][1];
            float v2 = acc[im][in][2], v3 = acc[im][in][3];
            if (OUTR) { v0 = rnd(v0); v1 = rnd(v1); v2 = rnd(v2); v3 = rnd(v3); }
            if (OUTM == 0) {
                *reinterpret_cast<float2*>(C + (long)r * ldc + cc) = make_float2(v0, v1);
                *reinterpret_cast<float2*>(C + (long)(r + 8) * ldc + cc) = make_float2(v2, v3);
            } else {
                int s0 = g_slot[(long)r * F_ + cc];
                int s1 = g_slot[(long)r * F_ + cc + 1];
                int s2 = g_slot[(long)(r + 8) * F_ + cc];
                int s3 = g_slot[(long)(r + 8) * F_ + cc + 1];
                if (s0 >= 0) g_vwval[(long)zh * NNZCAP + s0] = v0;
                if (s1 >= 0) g_vwval[(long)zh * NNZCAP + s1] = v1;
                if (s2 >= 0) g_vwval[(long)zh * NNZCAP + s2] = v2;
                if (s3 >= 0) g_vwval[(long)zh * NNZCAP + s3] = v3;
            }
        }
    }
}

// ---------------- spMM: Yt[b,f,h*S+k] += sum_j uplnT[gidx[j],bk]*vwval[h,j] --
constexpr int FT2 = 8;

__global__ __launch_bounds__(256)
void spmm_k() {
    const int t = threadIdx.x;
    const int bk = blockIdx.x * 256 + t;
    const int f0 = blockIdx.y * FT2;

    float acc[FT2][H_];
    #pragma unroll
    for (int i = 0; i < FT2; i++)
        #pragma unroll
        for (int h = 0; h < H_; h++) acc[i][h] = 0.f;

    #pragma unroll 1
    for (int fi = 0; fi < FT2; fi++) {
        const int f = f0 + fi;
        int j = g_rowptr[f];
        const int je = g_rowptr[f + 1];
        for (; j + 1 < je; j += 2) {
            int   ga = g_gidx[j], gb = g_gidx[j + 1];
            float xa = g_uplnT[(long)ga * BS_ + bk];
            float xb = g_uplnT[(long)gb * BS_ + bk];
            #pragma unroll
            for (int h = 0; h < H_; h++) {
                const float* vp = g_vwval + (long)h * NNZCAP + j;
                acc[fi][h] += xa * vp[0];
                acc[fi][h] += xb * vp[1];
            }
        }
        for (; j < je; j++) {
            int g = g_gidx[j];
            float x = g_uplnT[(long)g * BS_ + bk];
            #pragma unroll
            for (int h = 0; h < H_; h++)
                acc[fi][h] += x * g_vwval[(long)h * NNZCAP + j];
        }
    }

    const int b = bk >> 9, k = bk & (S_ - 1);
    #pragma unroll 1
    for (int fi = 0; fi < FT2; fi++) {
        long base = ((long)b * F_ + f0 + fi) * HK_ + k;
        #pragma unroll
        for (int h = 0; h < H_; h++) {
            float y = g_Yt[base + h * S_] + acc[fi][h];
            g_Yt[base + h * S_] = rnd(y);   // Yt is a tf32 GEMM operand for step 6
        }
    }
}

// ---------------------------------------------------------------------------
extern "C" void kernel_launch(void* const* d_in, const int* in_sizes, int n_in,
                              void* d_out, int out_size) {
    (void)in_sizes; (void)n_in; (void)out_size;
    const float* act   = (const float*)d_in[0];
    const float* lns   = (const float*)d_in[1];
    const float* probs = (const float*)d_in[2];
    const float* pf    = (const float*)d_in[3];
    const float* W_O   = (const float*)d_in[4];
    const float* W_V   = (const float*)d_in[5];
    const float* W_enc = (const float*)d_in[6];
    const float* b_enc = (const float*)d_in[7];
    const float* b_dec = (const float*)d_in[8];
    const float* W_dec = (const float*)d_in[9];
    const float* upb   = (const float*)d_in[10];
    const unsigned char* mask = (const unsigned char*)d_in[11];
    float* out = (float*)d_out;

    float *WOV, *A1, *WdT, *WeR, *xln, *pR, *Yt;
    cudaGetSymbolAddress((void**)&WOV, g_WOV);
    cudaGetSymbolAddress((void**)&A1,  g_A1);
    cudaGetSymbolAddress((void**)&WdT, g_WdecT);
    cudaGetSymbolAddress((void**)&WeR, g_WencR);
    cudaGetSymbolAddress((void**)&xln, g_xln);
    cudaGetSymbolAddress((void**)&pR,  g_probsR);
    cudaGetSymbolAddress((void**)&Yt,  g_Yt);

    const long DD = (long)D_ * D_;
    const long FD = (long)F_ * D_;
    const long SD = (long)S_ * D_;
    const long SS = (long)S_ * S_;
    const long FHK = (long)F_ * HK_;

    cudaFuncSetAttribute(mma_k<0, 0, 1>, cudaFuncAttributeMaxDynamicSharedMemorySize, MMA_SMEM);
    cudaFuncSetAttribute(mma_k<0, 2, 0>, cudaFuncAttributeMaxDynamicSharedMemorySize, MMA_SMEM);
    cudaFuncSetAttribute(mma_k<1, 0, 0>, cudaFuncAttributeMaxDynamicSharedMemorySize, MMA_SMEM);

    detect_mask_k<<<1, 32>>>(mask);
    count_k<<<(F_ * 32 + 255) / 256, 256>>>(mask);
    scan_k<<<1, 256>>>();
    fill_k<<<(F_ * 32 + 255) / 256, 256>>>(mask);

    {
        long tot = (long)B_ * S_ * D_;
        prep_x_k<<<(int)((tot + 255) / 256), 256>>>(act, lns);
    }
    round_wenc_k<<<(int)(((long)F_ * D_ + 255) / 256), 256>>>(W_enc);
    round_probs_k<<<(int)(((long)B_ * H_ * S_ * S_ + 255) / 256), 256>>>(probs);
    prep_upT_k<<<dim3(F_ / 32, BS_ / 32), dim3(32, 8)>>>(pf, lns);
    tpose_wdec_k<<<dim3(F_ / 32, D_ / 32), dim3(32, 8)>>>(W_dec);

    // 1) W_OV[h] = W_V[h] @ W_O[h]   (FFMA; output tf32-rounded)
    sgemm_nn_k<<<dim3(D_ / BN, D_ / BM, H_), 256>>>(
        W_V, W_O, WOV, DH_, DH_, D_, D_,
        (long)D_ * DH_, (long)DH_ * D_, DD);

    c_k<<<dim3(3, H_, 8), 256>>>(upb);
    bias_vec_k<<<F_ / 256, 256>>>(W_enc, b_enc, b_dec);

    // 3) A1[h][f][m] = WencR[f,:] . WOV[h][m,:]   M=2048 N=768 K=768  (round out)
    mma_k<0, 0, 1><<<dim3(D_ / 128, F_ / 128, H_), 256, MMA_SMEM>>>(
        WeR, WOV, A1, D_, D_, D_, D_, H_,
        0, 0, 0, DD, 0, FD);

    // 4) vw[h][f][g] = A1[h][f,:] . WdecT[g,:] -> masked scatter  M=2048 N=2048 K=768
    mma_k<0, 2, 0><<<dim3(F_ / 128, F_ / 128, H_), 256, MMA_SMEM>>>(
        A1, WdT, xln /*unused*/, D_, D_, D_, 0, H_,
        0, FD, 0, 0, 0, 0);

    // 5a) Yt[b][f][h*S+k] = A1[h][f,:] . xln[b][k,:]   M=2048 N=512 K=768  (round out)
    mma_k<0, 0, 1><<<dim3(S_ / 128, F_ / 128, B_ * H_), 256, MMA_SMEM>>>(
        A1, xln, Yt, D_, D_, D_, HK_, H_,
        0, FD, SD, 0, FHK, (long)S_);

    // 5b) sparse accumulate into Yt (re-rounds)
    spmm_k<<<dim3(BS_ / 256, F_ / FT2), 256>>>();

    // 6) out[b][q][f] = probsR[b][q,:] . Yt[b][f,:]   M=512 N=2048 K=6144 (fp32 out)
    mma_k<1, 0, 0><<<dim3(F_ / 128, S_ / 128, B_), 256, MMA_SMEM>>>(
        pR, Yt, out, HK_, 0, HK_, F_, 1,
        (long)H_ * SS, 0, FHK, 0, (long)S_ * F_, 0);

    // 7) out += bias0[f] + e[f] / ln_scale
    {
        long tot = (long)B_ * S_ * F_;
        finish_k<<<(int)((tot + 255) / 256), 256>>>(out, lns);
    }
}

// round 7
// speedup vs baseline: 3.7738x; 1.0124x over previous
#include <cuda_runtime.h>

// Problem constants
#define B_  4
#define S_  512
#define D_  768
#define H_  12
#define DH_ 64
#define F_  2048
#define BS_ (B_ * S_)          // 2048
#define HK_ (H_ * S_)          // 6144
#define NNZCAP 262144          // cap on mask nonzeros (expected ~210K)

// ---------------- scratch (device globals; no allocations allowed) ----------
__device__ float g_WOV  [H_ * D_ * D_];      // [h][m][o]   tf32-rounded
__device__ float g_A1   [H_ * F_ * D_];      // [h][f][m]   tf32-rounded
__device__ float g_WdecT[F_ * D_];           // [g][m]      tf32-rounded
__device__ float g_WencR[F_ * D_];           // rounded copy of W_enc
__device__ float g_xln  [B_ * S_ * D_];      // tf32-rounded
__device__ float g_probsR[B_ * H_ * S_ * S_];// rounded copy of probs
__device__ float g_uplnT[F_ * BS_];          // [g][bk] fp32
__device__ float g_Yt   [B_ * F_ * HK_];     // [b][f][h*S+k] tf32-rounded
__device__ float g_vwval[H_ * NNZCAP];       // fp32 compact masked vw
__device__ int   g_gidx [NNZCAP];
__device__ int   g_cnt  [F_];
__device__ int   g_rowptr[F_ + 1];
__device__ float g_c    [D_];
__device__ float g_bias0[F_];
__device__ float g_e    [F_];
__device__ int   g_maskmode;

__device__ __forceinline__ unsigned f2tf32(float x) {
    unsigned r;
    asm("cvt.rna.tf32.f32 %0, %1;" : "=r"(r) : "f"(x));
    return r;
}
__device__ __forceinline__ float rnd(float x) { return __uint_as_float(f2tf32(x)); }

// ---------------- mask dtype detector ---------------------------------------
__global__ void detect_mask_k(const unsigned char* __restrict__ m) {
    if (threadIdx.x != 0 || blockIdx.x != 0) return;
    int sawF = 0, sawB = 0;
    for (int i = 0; i < 65536; i++) {
        unsigned char v = m[i];
        if (v == 63 || v == 128) sawF = 1;
        else if (v != 0 && (i & 3) != 0) sawB = 1;
    }
    g_maskmode = sawF ? 2 : (sawB ? 0 : 1);
}

__device__ __forceinline__ int mask_nz(const unsigned char* m, long idx, int mode) {
    if (mode == 0) return m[idx] != 0;
    if (mode == 1) return ((const int*)m)[idx] != 0;
    return ((const float*)m)[idx] != 0.f;
}

// ---------------- mask CSR builders -----------------------------------------
__global__ void count_k(const unsigned char* __restrict__ m) {
    int w = (blockIdx.x * blockDim.x + threadIdx.x) >> 5;
    int lane = threadIdx.x & 31;
    if (w >= F_) return;
    int mode = g_maskmode;
    int cnt = 0;
    for (int g0 = 0; g0 < F_; g0 += 32) {
        int v = mask_nz(m, (long)w * F_ + g0 + lane, mode);
        cnt += __popc(__ballot_sync(0xffffffffu, v));
    }
    if (lane == 0) g_cnt[w] = cnt;
}

__global__ void scan_k() {
    __shared__ int part[256];
    int t = threadIdx.x;
    int base = t * 8;
    int s = 0;
    for (int i = 0; i < 8; i++) s += g_cnt[base + i];
    part[t] = s;
    __syncthreads();
    if (t == 0) {
        int r = 0;
        for (int i = 0; i < 256; i++) { int v = part[i]; part[i] = r; r += v; }
        g_rowptr[F_] = r;
    }
    __syncthreads();
    int r = part[t];
    for (int i = 0; i < 8; i++) { g_rowptr[base + i] = r; r += g_cnt[base + i]; }
}

__global__ void fill_k(const unsigned char* __restrict__ m) {
    int w = (blockIdx.x * blockDim.x + threadIdx.x) >> 5;
    int lane = threadIdx.x & 31;
    if (w >= F_) return;
    int mode = g_maskmode;
    int base = g_rowptr[w];
    unsigned lt = (1u << lane) - 1u;
    for (int g0 = 0; g0 < F_; g0 += 32) {
        int g = g0 + lane;
        int v = mask_nz(m, (long)w * F_ + g, mode);
        unsigned bal = __ballot_sync(0xffffffffu, v);
        int pos = base + __popc(bal & lt);
        if (v && pos < NNZCAP) g_gidx[pos] = g;
        base += __popc(bal);
    }
}

// ---------------- elementwise prep ------------------------------------------
__global__ void prep_x_k(const float* __restrict__ act, const float* __restrict__ lns) {
    long i = (long)blockIdx.x * blockDim.x + threadIdx.x;
    if (i < (long)B_ * S_ * D_) g_xln[i] = rnd(act[i] / lns[i / D_]);
    if (i < D_) g_c[i] = 0.f;
}

__global__ void round_wenc_k(const float* __restrict__ w) {
    long i = (long)blockIdx.x * blockDim.x + threadIdx.x;
    if (i < (long)F_ * D_) g_WencR[i] = rnd(w[i]);
}
__global__ void round_probs_k(const float* __restrict__ p) {
    long i = (long)blockIdx.x * blockDim.x + threadIdx.x;
    long tot = (long)B_ * H_ * S_ * S_;
    if (i < tot) g_probsR[i] = rnd(p[i]);
}

__global__ void prep_upT_k(const float* __restrict__ pf, const float* __restrict__ lns) {
    __shared__ float tile[32][33];
    int tx = threadIdx.x, ty = threadIdx.y;
    int g = blockIdx.x * 32 + tx;
    int bk0 = blockIdx.y * 32;
    #pragma unroll
    for (int i = 0; i < 32; i += 8) {
        int bk = bk0 + ty + i;
        tile[ty + i][tx] = pf[(long)bk * F_ + g] / lns[bk];
    }
    __syncthreads();
    int bkOut = bk0 + tx;
    #pragma unroll
    for (int i = 0; i < 32; i += 8)
        g_uplnT[(long)(blockIdx.x * 32 + ty + i) * BS_ + bkOut] = tile[tx][ty + i];
}

// W_decT[g][m] = W_dec[m][g]   (rounded)
__global__ void tpose_wdec_k(const float* __restrict__ wd) {
    __shared__ float tile[32][33];
    int tx = threadIdx.x, ty = threadIdx.y;
    int g = blockIdx.x * 32 + tx;
    int m0 = blockIdx.y * 32;
    #pragma unroll
    for (int i = 0; i < 32; i += 8)
        tile[ty + i][tx] = wd[(long)(m0 + ty + i) * F_ + g];
    __syncthreads();
    int mOut = m0 + tx;
    #pragma unroll
    for (int i = 0; i < 32; i += 8)
        g_WdecT[(long)(blockIdx.x * 32 + ty + i) * D_ + mOut] = rnd(tile[tx][ty + i]);
}

// ---------------- bias vectors ----------------------------------------------
__global__ void c_k(const float* __restrict__ upb) {
    int d = blockIdx.x * 256 + threadIdx.x;
    int h = blockIdx.y;
    int m0 = blockIdx.z * 96;
    if (d >= D_) return;
    const float* base = g_WOV + (long)h * D_ * D_;
    float s = 0.f;
    for (int m = m0; m < m0 + 96; m++) s += base[(long)m * D_ + d] * upb[m];
    atomicAdd(&g_c[d], s);
}

__global__ void bias_vec_k(const float* __restrict__ W_enc,
                           const float* __restrict__ b_enc,
                           const float* __restrict__ b_dec) {
    int f = blockIdx.x * 256 + threadIdx.x;
    if (f >= F_) return;
    const float* row = W_enc + (long)f * D_;
    float s0 = 0.f, s1 = 0.f;
    for (int d = 0; d < D_; d++) {
        float w = row[d];
        s0 += w * b_dec[d];
        s1 += w * g_c[d];
    }
    g_bias0[f] = b_enc[f] - s0;
    g_e[f] = s1;
}

__global__ void finish_k(float* __restrict__ out, const float* __restrict__ lns) {
    long i = (long)blockIdx.x * blockDim.x + threadIdx.x;
    if (i >= (long)B_ * S_ * F_) return;
    int f = (int)(i & (F_ - 1));
    long row = i >> 11;
    out[i] += g_bias0[f] + g_e[f] / lns[row];
}

// ---------------- FFMA SGEMM (step 1 only: small) ----------------------------
constexpr int BM = 128, BN = 128, BKK = 8, TM = 8, TN = 8;

__global__ __launch_bounds__(256)
void sgemm_nn_k(const float* __restrict__ A, const float* __restrict__ B,
                float* __restrict__ C, int K, int lda, int ldb, int ldc,
                long sAh, long sBh, long sCh) {
    const int zh = blockIdx.z;
    A += zh * sAh; B += zh * sBh; C += zh * sCh;

    __shared__ float As[BKK][BM + 4];
    __shared__ float Bs[BKK][BN + 4];

    const int tid = threadIdx.x;
    const int tx = tid & 15, ty = tid >> 4;
    const int row0 = blockIdx.y * BM, col0 = blockIdx.x * BN;
    const int aRow = tid >> 1, aCol = (tid & 1) << 2;
    const int bR = tid >> 5, bC = (tid & 31) << 2;

    float acc[TM][TN];
    #pragma unroll
    for (int i = 0; i < TM; i++)
        #pragma unroll
        for (int j = 0; j < TN; j++) acc[i][j] = 0.f;

    for (int k0 = 0; k0 < K; k0 += BKK) {
        float4 av = *reinterpret_cast<const float4*>(A + (long)(row0 + aRow) * lda + k0 + aCol);
        As[aCol + 0][aRow] = av.x; As[aCol + 1][aRow] = av.y;
        As[aCol + 2][aRow] = av.z; As[aCol + 3][aRow] = av.w;
        float4 bv = *reinterpret_cast<const float4*>(B + (long)(k0 + bR) * ldb + col0 + bC);
        *reinterpret_cast<float4*>(&Bs[bR][bC]) = bv;
        __syncthreads();
        #pragma unroll
        for (int kk = 0; kk < BKK; kk++) {
            float a[TM], bb[TN];
            #pragma unroll
            for (int i = 0; i < TM; i++) a[i] = As[kk][ty * TM + i];
            #pragma unroll
            for (int j = 0; j < TN; j++) bb[j] = Bs[kk][tx * TN + j];
            #pragma unroll
            for (int i = 0; i < TM; i++)
                #pragma unroll
                for (int j = 0; j < TN; j++) acc[i][j] += a[i] * bb[j];
        }
        __syncthreads();
    }
    #pragma unroll
    for (int i = 0; i < TM; i++) {
        long r = row0 + ty * TM + i;
        #pragma unroll
        for (int j = 0; j < TN; j++)
            C[r * ldc + col0 + tx * TN + j] = rnd(acc[i][j]);  // tf32-rounded (GEMM operand)
    }
}

// ================ tf32 mma.sync GEMM, cp.async 3-stage + ldmatrix (NT) =======
// C[M,N] = A[M,K] * B[N,K]^T.  Block 128x128, K-chunk 32, 8 warps 2(M)x4(N).
// Operands MUST be tf32-pre-rounded in gmem.
// Fragments via ldmatrix.b16 (tf32 m16n8k8 fragment map == b16 8x8 tiles).
// AMODE 0: A row-major [M,K] lda.  AMODE 1: A = probsR[b] piecewise per head.
// OUTR 1: tf32-round output.
#define MK   32
#define PAD  36
#define NSTG 3
#define STGF (128 * PAD)                      // floats per (A or B) stage
#define MMA_SMEM (NSTG * 2 * STGF * 4)        // 110592 bytes

__device__ __forceinline__ unsigned smem_u32(const void* p) {
    unsigned a;
    asm("{ .reg .u64 t; cvta.to.shared.u64 t, %1; cvt.u32.u64 %0, t; }" : "=r"(a) : "l"(p));
    return a;
}
__device__ __forceinline__ void cpasync16(unsigned dst, const void* src) {
    asm volatile("cp.async.cg.shared.global [%0], [%1], 16;" :: "r"(dst), "l"(src) : "memory");
}
__device__ __forceinline__ void ldsm_x4(unsigned addr, unsigned& r0, unsigned& r1,
                                        unsigned& r2, unsigned& r3) {
    asm volatile("ldmatrix.sync.aligned.m8n8.x4.shared.b16 {%0,%1,%2,%3}, [%4];"
                 : "=r"(r0), "=r"(r1), "=r"(r2), "=r"(r3) : "r"(addr));
}
__device__ __forceinline__ void ldsm_x2(unsigned addr, unsigned& r0, unsigned& r1) {
    asm volatile("ldmatrix.sync.aligned.m8n8.x2.shared.b16 {%0,%1}, [%2];"
                 : "=r"(r0), "=r"(r1) : "r"(addr));
}

template<int AMODE, int OUTR>
__global__ __launch_bounds__(256, 2)
void mma_k(const float* __restrict__ Ag, const float* __restrict__ Bg,
           float* __restrict__ Cg,
           int K, int lda, int ldb, int ldc, int Hdim,
           long sAb, long sAh, long sBb, long sBh, long sCb, long sCh) {
    extern __shared__ __align__(16) float sm[];

    const int zb = blockIdx.z / Hdim, zh = blockIdx.z % Hdim;
    const float* A = Ag + zb * sAb + zh * sAh;
    const float* B = Bg + zb * sBb + zh * sBh;
    float* C = Cg + zb * sCb + zh * sCh;

    const int row0 = blockIdx.y * 128, col0 = blockIdx.x * 128;
    const int tid = threadIdx.x, wid = tid >> 5, lane = tid & 31;
    const int warpM = (wid & 1) * 64, warpN = (wid >> 1) * 32;
    const int lr = lane >> 2, lc = lane & 3;

    float acc[4][4][4];
    #pragma unroll
    for (int im = 0; im < 4; im++)
        #pragma unroll
        for (int in = 0; in < 4; in++)
            #pragma unroll
            for (int q = 0; q < 4; q++) acc[im][in][q] = 0.f;

    const int nch = K / MK;
    const int ur = tid >> 3, uc = (tid & 7) * 4;   // cp.async: 32 rows x 8 quads / pass

    // ldmatrix lane->row/col mapping (byte offsets within a stage)
    const unsigned sb32 = smem_u32(sm);
    const int lrow8 = lane & 7, sel = lane >> 3;
    const unsigned aoff = (unsigned)(((warpM + (sel & 1) * 8 + lrow8) * PAD
                                      + (sel >> 1) * 4)) * 4u;
    const unsigned boff = (unsigned)(((warpN + lrow8) * PAD
                                      + ((lane >> 3) & 1) * 4)) * 4u;

    auto issue = [&](int c) {
        unsigned sa = sb32 + (unsigned)((c % NSTG) * 2 * STGF) * 4u;
        const int k0 = c * MK;
        #pragma unroll
        for (int i = 0; i < 4; i++) {
            int r = ur + i * 32;
            const float* srcA;
            if (AMODE == 0) srcA = A + (long)(row0 + r) * lda + k0 + uc;
            else {
                int kk = k0 + uc;
                srcA = A + (long)(kk >> 9) * (S_ * S_) + (long)(row0 + r) * S_ + (kk & (S_ - 1));
            }
            unsigned off = (unsigned)(r * PAD + uc) * 4u;
            cpasync16(sa + off, srcA);
            cpasync16(sa + (unsigned)STGF * 4u + off,
                      B + (long)(col0 + r) * ldb + k0 + uc);
        }
    };

    issue(0);
    asm volatile("cp.async.commit_group;" ::: "memory");
    issue(1);
    asm volatile("cp.async.commit_group;" ::: "memory");

    for (int c = 0; c < nch; c++) {
        asm volatile("cp.async.wait_group 1;" ::: "memory");
        __syncthreads();
        if (c + 2 < nch) issue(c + 2);
        asm volatile("cp.async.commit_group;" ::: "memory");  // one group per iter (maybe empty)

        const unsigned sAa = sb32 + (unsigned)((c % NSTG) * 2 * STGF) * 4u;
        const unsigned sBa = sAa + (unsigned)STGF * 4u;
        #pragma unroll
        for (int ks = 0; ks < 4; ks++) {
            unsigned af[4][4], bf[4][2];
            #pragma unroll
            for (int im = 0; im < 4; im++)
                ldsm_x4(sAa + aoff + (unsigned)((im * 16 * PAD + ks * 8) * 4),
                        af[im][0], af[im][1], af[im][2], af[im][3]);
            #pragma unroll
            for (int in = 0; in < 4; in++)
                ldsm_x2(sBa + boff + (unsigned)((in * 8 * PAD + ks * 8) * 4),
                        bf[in][0], bf[in][1]);
            #pragma unroll
            for (int im = 0; im < 4; im++)
                #pragma unroll
                for (int in = 0; in < 4; in++) {
                    asm volatile(
                        "mma.sync.aligned.m16n8k8.row.col.f32.tf32.tf32.f32 "
                        "{%0,%1,%2,%3}, {%4,%5,%6,%7}, {%8,%9}, {%0,%1,%2,%3};"
                        : "+f"(acc[im][in][0]), "+f"(acc[im][in][1]),
                          "+f"(acc[im][in][2]), "+f"(acc[im][in][3])
                        : "r"(af[im][0]), "r"(af[im][1]), "r"(af[im][2]), "r"(af[im][3]),
                          "r"(bf[in][0]), "r"(bf[in][1]));
                }
        }
    }

    // epilogue: c0,c1 at (r, cc..cc+1); c2,c3 at (r+8, cc..cc+1)
    #pragma unroll
    for (int im = 0; im < 4; im++) {
        int r = row0 + warpM + im * 16 + lr;
        #pragma unroll
        for (int in = 0; in < 4; in++) {
            int cc = col0 + warpN + in * 8 + lc * 2;
            float v0 = acc[im][in][0], v1 = acc[im][in][1];
            float v2 = acc[im][in][2], v3 = acc[im][in][3];
            if (OUTR) { v0 = rnd(v0); v1 = rnd(v1); v2 = rnd(v2); v3 = rnd(v3); }
            *reinterpret_cast<float2*>(C + (long)r * ldc + cc) = make_float2(v0, v1);
            *reinterpret_cast<float2*>(C + (long)(r + 8) * ldc + cc) = make_float2(v2, v3);
        }
    }
}

// ---------- sparse vw: vwval[h][j] = A1[h][f,:] . WdecT[g_j,:]  (fp32) -------
// block per f; warps take 4 masked g's per pass; all 12 heads at once.
#define GPG 4

__global__ __launch_bounds__(256)
void vw_sparse_k() {
    __shared__ float sA[H_][D_];   // 36 KB
    const int f = blockIdx.x;
    const int tid = threadIdx.x, wid = tid >> 5, lane = tid & 31;

    for (int i = tid; i < H_ * D_; i += 256) {
        int h = i / D_, m = i - h * D_;
        sA[h][m] = g_A1[((long)h * F_ + f) * D_ + m];
    }
    __syncthreads();

    int jb = g_rowptr[f], je = g_rowptr[f + 1];
    if (je > NNZCAP) je = NNZCAP;

    for (int j0 = jb + wid * GPG; j0 < je; j0 += 8 * GPG) {
        const int ng = min(GPG, je - j0);
        int gi[GPG];
        #pragma unroll
        for (int q = 0; q < GPG; q++)
            gi[q] = g_gidx[(q < ng) ? (j0 + q) : j0];

        float acc[GPG][H_];
        #pragma unroll
        for (int q = 0; q < GPG; q++)
            #pragma unroll
            for (int h = 0; h < H_; h++) acc[q][h] = 0.f;

        #pragma unroll
        for (int rep = 0; rep < 6; rep++) {
            const int m0 = rep * 128 + lane * 4;
            float4 wd[GPG];
            #pragma unroll
            for (int q = 0; q < GPG; q++)
                wd[q] = *reinterpret_cast<const float4*>(&g_WdecT[(long)gi[q] * D_ + m0]);
            #pragma unroll
            for (int h = 0; h < H_; h++) {
                float4 a = *reinterpret_cast<const float4*>(&sA[h][m0]);
                #pragma unroll
                for (int q = 0; q < GPG; q++) {
                    acc[q][h] += a.x * wd[q].x;
                    acc[q][h] += a.y * wd[q].y;
                    acc[q][h] += a.z * wd[q].z;
                    acc[q][h] += a.w * wd[q].w;
                }
            }
        }

        // butterfly reduce across the warp (all lanes end with full sums)
        #pragma unroll
        for (int off = 16; off > 0; off >>= 1)
            #pragma unroll
            for (int q = 0; q < GPG; q++)
                #pragma unroll
                for (int h = 0; h < H_; h++)
                    acc[q][h] += __shfl_xor_sync(0xffffffffu, acc[q][h], off);

        // distribute writes across lanes
        #pragma unroll
        for (int q = 0; q < GPG; q++)
            #pragma unroll
            for (int h = 0; h < H_; h++) {
                int v = q * H_ + h;
                if ((v & 31) == lane && q < ng)
                    g_vwval[(long)h * NNZCAP + j0 + q] = acc[q][h];
            }
    }
}

// ---------------- spMM: Yt[b,f,h*S+k] += sum_j uplnT[gidx[j],bk]*vwval[h,j] --
constexpr int FT2 = 8;

__global__ __launch_bounds__(256)
void spmm_k() {
    const int t = threadIdx.x;
    const int bk = blockIdx.x * 256 + t;
    const int f0 = blockIdx.y * FT2;

    float acc[FT2][H_];
    #pragma unroll
    for (int i = 0; i < FT2; i++)
        #pragma unroll
        for (int h = 0; h < H_; h++) acc[i][h] = 0.f;

    #pragma unroll 1
    for (int fi = 0; fi < FT2; fi++) {
        const int f = f0 + fi;
        int j = g_rowptr[f];
        int je = g_rowptr[f + 1];
        if (je > NNZCAP) je = NNZCAP;
        for (; j + 1 < je; j += 2) {
            int   ga = g_gidx[j], gb = g_gidx[j + 1];
            float xa = g_uplnT[(long)ga * BS_ + bk];
            float xb = g_uplnT[(long)gb * BS_ + bk];
            #pragma unroll
            for (int h = 0; h < H_; h++) {
                const float* vp = g_vwval + (long)h * NNZCAP + j;
                acc[fi][h] += xa * vp[0];
                acc[fi][h] += xb * vp[1];
            }
        }
        for (; j < je; j++) {
            int g = g_gidx[j];
            float x = g_uplnT[(long)g * BS_ + bk];
            #pragma unroll
            for (int h = 0; h < H_; h++)
                acc[fi][h] += x * g_vwval[(long)h * NNZCAP + j];
        }
    }

    const int b = bk >> 9, k = bk & (S_ - 1);
    #pragma unroll 1
    for (int fi = 0; fi < FT2; fi++) {
        long base = ((long)b * F_ + f0 + fi) * HK_ + k;
        #pragma unroll
        for (int h = 0; h < H_; h++) {
            float y = g_Yt[base + h * S_] + acc[fi][h];
            g_Yt[base + h * S_] = rnd(y);   // Yt is a tf32 GEMM operand for step 6
        }
    }
}

// ---------------------------------------------------------------------------
extern "C" void kernel_launch(void* const* d_in, const int* in_sizes, int n_in,
                              void* d_out, int out_size) {
    (void)in_sizes; (void)n_in; (void)out_size;
    const float* act   = (const float*)d_in[0];
    const float* lns   = (const float*)d_in[1];
    const float* probs = (const float*)d_in[2];
    const float* pf    = (const float*)d_in[3];
    const float* W_O   = (const float*)d_in[4];
    const float* W_V   = (const float*)d_in[5];
    const float* W_enc = (const float*)d_in[6];
    const float* b_enc = (const float*)d_in[7];
    const float* b_dec = (const float*)d_in[8];
    const float* W_dec = (const float*)d_in[9];
    const float* upb   = (const float*)d_in[10];
    const unsigned char* mask = (const unsigned char*)d_in[11];
    float* out = (float*)d_out;

    float *WOV, *A1, *WeR, *xln, *pR, *Yt;
    cudaGetSymbolAddress((void**)&WOV, g_WOV);
    cudaGetSymbolAddress((void**)&A1,  g_A1);
    cudaGetSymbolAddress((void**)&WeR, g_WencR);
    cudaGetSymbolAddress((void**)&xln, g_xln);
    cudaGetSymbolAddress((void**)&pR,  g_probsR);
    cudaGetSymbolAddress((void**)&Yt,  g_Yt);

    const long DD = (long)D_ * D_;
    const long FD = (long)F_ * D_;
    const long SD = (long)S_ * D_;
    const long SS = (long)S_ * S_;
    const long FHK = (long)F_ * HK_;

    cudaFuncSetAttribute(mma_k<0, 1>, cudaFuncAttributeMaxDynamicSharedMemorySize, MMA_SMEM);
    cudaFuncSetAttribute(mma_k<1, 0>, cudaFuncAttributeMaxDynamicSharedMemorySize, MMA_SMEM);

    detect_mask_k<<<1, 32>>>(mask);
    count_k<<<(F_ * 32 + 255) / 256, 256>>>(mask);
    scan_k<<<1, 256>>>();
    fill_k<<<(F_ * 32 + 255) / 256, 256>>>(mask);

    {
        long tot = (long)B_ * S_ * D_;
        prep_x_k<<<(int)((tot + 255) / 256), 256>>>(act, lns);
    }
    round_wenc_k<<<(int)(((long)F_ * D_ + 255) / 256), 256>>>(W_enc);
    round_probs_k<<<(int)(((long)B_ * H_ * S_ * S_ + 255) / 256), 256>>>(probs);
    prep_upT_k<<<dim3(F_ / 32, BS_ / 32), dim3(32, 8)>>>(pf, lns);
    tpose_wdec_k<<<dim3(F_ / 32, D_ / 32), dim3(32, 8)>>>(W_dec);

    // 1) W_OV[h] = W_V[h] @ W_O[h]   (FFMA; output tf32-rounded)
    sgemm_nn_k<<<dim3(D_ / BN, D_ / BM, H_), 256>>>(
        W_V, W_O, WOV, DH_, DH_, D_, D_,
        (long)D_ * DH_, (long)DH_ * D_, DD);

    c_k<<<dim3(3, H_, 8), 256>>>(upb);
    bias_vec_k<<<F_ / 256, 256>>>(W_enc, b_enc, b_dec);

    // 3) A1[h][f][m] = WencR[f,:] . WOV[h][m,:]   M=2048 N=768 K=768  (round out)
    mma_k<0, 1><<<dim3(D_ / 128, F_ / 128, H_), 256, MMA_SMEM>>>(
        WeR, WOV, A1, D_, D_, D_, D_, H_,
        0, 0, 0, DD, 0, FD);

    // 4) sparse vw: vwval[h][j] = A1[h][f,:] . WdecT[g_j,:]  (fp32 direct)
    vw_sparse_k<<<F_, 256>>>();

    // 5a) Yt[b][f][h*S+k] = A1[h][f,:] . xln[b][k,:]   M=2048 N=512 K=768  (round out)
    mma_k<0, 1><<<dim3(S_ / 128, F_ / 128, B_ * H_), 256, MMA_SMEM>>>(
        A1, xln, Yt, D_, D_, D_, HK_, H_,
        0, FD, SD, 0, FHK, (long)S_);

    // 5b) sparse accumulate into Yt (re-rounds)
    spmm_k<<<dim3(BS_ / 256, F_ / FT2), 256>>>();

    // 6) out[b][q][f] = probsR[b][q,:] . Yt[b][f,:]   M=512 N=2048 K=6144 (fp32 out)
    mma_k<1, 0><<<dim3(F_ / 128, S_ / 128, B_), 256, MMA_SMEM>>>(
        pR, Yt, out, HK_, 0, HK_, F_, 1,
        (long)H_ * SS, 0, FHK, 0, (long)S_ * F_, 0);

    // 7) out += bias0[f] + e[f] / ln_scale
    {
        long tot = (long)B_ * S_ * F_;
        finish_k<<<(int)((tot + 255) / 256), 256>>>(out, lns);
    }
}

// round 8
// speedup vs baseline: 5.8421x; 1.5481x over previous
#include <cuda_runtime.h>
#include <cuda_fp16.h>

// Problem constants
#define B_  4
#define S_  512
#define D_  768
#define H_  12
#define DH_ 64
#define F_  2048
#define BS_ (B_ * S_)          // 2048
#define HK_ (H_ * S_)          // 6144
#define NNZCAP 262144          // cap on mask nonzeros (expected ~210K)

// ---------------- scratch (device globals; no allocations allowed) ----------
__device__ float  g_WOV  [H_ * D_ * D_];      // [h][m][o] fp32
__device__ __half g_WOVh [H_ * D_ * D_];      // half copy (GEMM operand)
__device__ float  g_A1   [H_ * F_ * D_];      // [h][f][m] fp32 (sparse vw input)
__device__ __half g_A1h  [H_ * F_ * D_];      // half copy (GEMM operand)
__device__ float  g_WdecT[F_ * D_];           // [g][m] fp32
__device__ __half g_WencH[F_ * D_];           // half W_enc
__device__ __half g_xlnH [B_ * S_ * D_];      // half x_ln
__device__ __half g_probsH[B_ * H_ * S_ * S_];// half probs
__device__ float  g_uplnT[F_ * BS_];          // [g][bk] fp32
__device__ __half g_YtH  [B_ * F_ * HK_];     // [b][f][h*S+k] half
__device__ float  g_vwval[H_ * NNZCAP];       // fp32 compact masked vw
__device__ int    g_gidx [NNZCAP];
__device__ int    g_cnt  [F_];
__device__ int    g_rowptr[F_ + 1];
__device__ float  g_c    [D_];
__device__ float  g_bias0[F_];
__device__ float  g_e    [F_];
__device__ int    g_maskmode;

// ---------------- mask dtype detector (parallel) -----------------------------
__global__ void detect_mask_k(const unsigned char* __restrict__ m) {
    __shared__ int sF, sB;
    int tid = threadIdx.x;
    if (tid == 0) { sF = 0; sB = 0; }
    __syncthreads();
    int f = 0, b = 0;
    for (int i = tid; i < 65536; i += 256) {
        unsigned char v = m[i];
        if (v == 63 || v == 128) f = 1;
        else if (v != 0 && (i & 3) != 0) b = 1;
    }
    if (f) atomicOr(&sF, 1);
    if (b) atomicOr(&sB, 1);
    __syncthreads();
    if (tid == 0) g_maskmode = sF ? 2 : (sB ? 0 : 1);
}

__device__ __forceinline__ int mask_nz(const unsigned char* m, long idx, int mode) {
    if (mode == 0) return m[idx] != 0;
    if (mode == 1) return ((const int*)m)[idx] != 0;
    return ((const float*)m)[idx] != 0.f;
}

// ---------------- mask CSR builders -----------------------------------------
__global__ void count_k(const unsigned char* __restrict__ m) {
    int w = (blockIdx.x * blockDim.x + threadIdx.x) >> 5;
    int lane = threadIdx.x & 31;
    if (w >= F_) return;
    int mode = g_maskmode;
    int cnt = 0;
    for (int g0 = 0; g0 < F_; g0 += 32) {
        int v = mask_nz(m, (long)w * F_ + g0 + lane, mode);
        cnt += __popc(__ballot_sync(0xffffffffu, v));
    }
    if (lane == 0) g_cnt[w] = cnt;
}

__global__ void scan_k() {
    __shared__ int part[256];
    int t = threadIdx.x;
    int base = t * 8;
    int s = 0;
    for (int i = 0; i < 8; i++) s += g_cnt[base + i];
    part[t] = s;
    __syncthreads();
    if (t == 0) {
        int r = 0;
        for (int i = 0; i < 256; i++) { int v = part[i]; part[i] = r; r += v; }
        g_rowptr[F_] = r;
    }
    __syncthreads();
    int r = part[t];
    for (int i = 0; i < 8; i++) { g_rowptr[base + i] = r; r += g_cnt[base + i]; }
}

__global__ void fill_k(const unsigned char* __restrict__ m) {
    int w = (blockIdx.x * blockDim.x + threadIdx.x) >> 5;
    int lane = threadIdx.x & 31;
    if (w >= F_) return;
    int mode = g_maskmode;
    int base = g_rowptr[w];
    unsigned lt = (1u << lane) - 1u;
    for (int g0 = 0; g0 < F_; g0 += 32) {
        int g = g0 + lane;
        int v = mask_nz(m, (long)w * F_ + g, mode);
        unsigned bal = __ballot_sync(0xffffffffu, v);
        int pos = base + __popc(bal & lt);
        if (v && pos < NNZCAP) g_gidx[pos] = g;
        base += __popc(bal);
    }
}

// ---------------- elementwise prep ------------------------------------------
__global__ void prep_x_k(const float* __restrict__ act, const float* __restrict__ lns) {
    long i = (long)blockIdx.x * blockDim.x + threadIdx.x;
    if (i < (long)B_ * S_ * D_) g_xlnH[i] = __float2half(act[i] / lns[i / D_]);
    if (i < D_) g_c[i] = 0.f;
}

__global__ void half_wenc_k(const float* __restrict__ w) {
    long i = (long)blockIdx.x * blockDim.x + threadIdx.x;
    if (i < (long)F_ * D_) g_WencH[i] = __float2half(w[i]);
}
__global__ void half_probs_k(const float* __restrict__ p) {
    long i = (long)blockIdx.x * blockDim.x + threadIdx.x;
    if (i < (long)B_ * H_ * S_ * S_) g_probsH[i] = __float2half(p[i]);
}
__global__ void half_wov_k() {
    long i = (long)blockIdx.x * blockDim.x + threadIdx.x;
    if (i < (long)H_ * D_ * D_) g_WOVh[i] = __float2half(g_WOV[i]);
}

__global__ void prep_upT_k(const float* __restrict__ pf, const float* __restrict__ lns) {
    __shared__ float tile[32][33];
    int tx = threadIdx.x, ty = threadIdx.y;
    int g = blockIdx.x * 32 + tx;
    int bk0 = blockIdx.y * 32;
    #pragma unroll
    for (int i = 0; i < 32; i += 8) {
        int bk = bk0 + ty + i;
        tile[ty + i][tx] = pf[(long)bk * F_ + g] / lns[bk];
    }
    __syncthreads();
    int bkOut = bk0 + tx;
    #pragma unroll
    for (int i = 0; i < 32; i += 8)
        g_uplnT[(long)(blockIdx.x * 32 + ty + i) * BS_ + bkOut] = tile[tx][ty + i];
}

// W_decT[g][m] = W_dec[m][g]   (fp32)
__global__ void tpose_wdec_k(const float* __restrict__ wd) {
    __shared__ float tile[32][33];
    int tx = threadIdx.x, ty = threadIdx.y;
    int g = blockIdx.x * 32 + tx;
    int m0 = blockIdx.y * 32;
    #pragma unroll
    for (int i = 0; i < 32; i += 8)
        tile[ty + i][tx] = wd[(long)(m0 + ty + i) * F_ + g];
    __syncthreads();
    int mOut = m0 + tx;
    #pragma unroll
    for (int i = 0; i < 32; i += 8)
        g_WdecT[(long)(blockIdx.x * 32 + ty + i) * D_ + mOut] = tile[tx][ty + i];
}

// ---------------- bias vectors ----------------------------------------------
__global__ void c_k(const float* __restrict__ upb) {
    int d = blockIdx.x * 256 + threadIdx.x;
    int h = blockIdx.y;
    int m0 = blockIdx.z * 96;
    if (d >= D_) return;
    const float* base = g_WOV + (long)h * D_ * D_;
    float s = 0.f;
    for (int m = m0; m < m0 + 96; m++) s += base[(long)m * D_ + d] * upb[m];
    atomicAdd(&g_c[d], s);
}

__global__ void bias_vec_k(const float* __restrict__ W_enc,
                           const float* __restrict__ b_enc,
                           const float* __restrict__ b_dec) {
    int f = blockIdx.x * 256 + threadIdx.x;
    if (f >= F_) return;
    const float* row = W_enc + (long)f * D_;
    float s0 = 0.f, s1 = 0.f;
    for (int d = 0; d < D_; d++) {
        float w = row[d];
        s0 += w * b_dec[d];
        s1 += w * g_c[d];
    }
    g_bias0[f] = b_enc[f] - s0;
    g_e[f] = s1;
}

__global__ void finish_k(float* __restrict__ out, const float* __restrict__ lns) {
    long i = (long)blockIdx.x * blockDim.x + threadIdx.x;
    if (i >= (long)B_ * S_ * F_) return;
    int f = (int)(i & (F_ - 1));
    long row = i >> 11;
    out[i] += g_bias0[f] + g_e[f] / lns[row];
}

// ---------------- FFMA SGEMM (step 1 only: small) ----------------------------
constexpr int BM = 128, BN = 128, BKK = 8, TM = 8, TN = 8;

__global__ __launch_bounds__(256)
void sgemm_nn_k(const float* __restrict__ A, const float* __restrict__ B,
                float* __restrict__ C, int K, int lda, int ldb, int ldc,
                long sAh, long sBh, long sCh) {
    const int zh = blockIdx.z;
    A += zh * sAh; B += zh * sBh; C += zh * sCh;

    __shared__ float As[BKK][BM + 4];
    __shared__ float Bs[BKK][BN + 4];

    const int tid = threadIdx.x;
    const int tx = tid & 15, ty = tid >> 4;
    const int row0 = blockIdx.y * BM, col0 = blockIdx.x * BN;
    const int aRow = tid >> 1, aCol = (tid & 1) << 2;
    const int bR = tid >> 5, bC = (tid & 31) << 2;

    float acc[TM][TN];
    #pragma unroll
    for (int i = 0; i < TM; i++)
        #pragma unroll
        for (int j = 0; j < TN; j++) acc[i][j] = 0.f;

    for (int k0 = 0; k0 < K; k0 += BKK) {
        float4 av = *reinterpret_cast<const float4*>(A + (long)(row0 + aRow) * lda + k0 + aCol);
        As[aCol + 0][aRow] = av.x; As[aCol + 1][aRow] = av.y;
        As[aCol + 2][aRow] = av.z; As[aCol + 3][aRow] = av.w;
        float4 bv = *reinterpret_cast<const float4*>(B + (long)(k0 + bR) * ldb + col0 + bC);
        *reinterpret_cast<float4*>(&Bs[bR][bC]) = bv;
        __syncthreads();
        #pragma unroll
        for (int kk = 0; kk < BKK; kk++) {
            float a[TM], bb[TN];
            #pragma unroll
            for (int i = 0; i < TM; i++) a[i] = As[kk][ty * TM + i];
            #pragma unroll
            for (int j = 0; j < TN; j++) bb[j] = Bs[kk][tx * TN + j];
            #pragma unroll
            for (int i = 0; i < TM; i++)
                #pragma unroll
                for (int j = 0; j < TN; j++) acc[i][j] += a[i] * bb[j];
        }
        __syncthreads();
    }
    #pragma unroll
    for (int i = 0; i < TM; i++) {
        long r = row0 + ty * TM + i;
        #pragma unroll
        for (int j = 0; j < TN; j++)
            C[r * ldc + col0 + tx * TN + j] = acc[i][j];
    }
}

// ====== fp16 mma.sync m16n8k16 GEMM, cp.async 3-stage + ldmatrix (NT) ========
// C[M,N] = A[M,K] * B[N,K]^T, fp16 in / fp32 acc.
// Block 128x128, K-chunk 64 (4 k-steps of 16), 8 warps 2(M)x4(N).
// AMODE 0: A row-major [M,K] lda.  AMODE 1: A = probsH[b] piecewise per head.
// OUTM 0: fp32 C.  1: half Ch.  2: both (C fp32 + Ch half).
// CAUSAL 1 (with AMODE 1): per q-block keep only k-chunks with koff < row0+128.
#define MK   64
#define ROWH 72                               // halfs per smem row (64 + 8 pad)
#define NSTG 3
#define STGB (128 * ROWH * 2)                 // bytes per operand stage (18432)
#define MMA_SMEM (NSTG * 2 * STGB)            // 110592 bytes

__device__ __forceinline__ unsigned smem_u32(const void* p) {
    unsigned a;
    asm("{ .reg .u64 t; cvta.to.shared.u64 t, %1; cvt.u32.u64 %0, t; }" : "=r"(a) : "l"(p));
    return a;
}
__device__ __forceinline__ void cpasync16(unsigned dst, const void* src) {
    asm volatile("cp.async.cg.shared.global [%0], [%1], 16;" :: "r"(dst), "l"(src) : "memory");
}
__device__ __forceinline__ void ldsm_x4(unsigned addr, unsigned& r0, unsigned& r1,
                                        unsigned& r2, unsigned& r3) {
    asm volatile("ldmatrix.sync.aligned.m8n8.x4.shared.b16 {%0,%1,%2,%3}, [%4];"
                 : "=r"(r0), "=r"(r1), "=r"(r2), "=r"(r3) : "r"(addr));
}
__device__ __forceinline__ void ldsm_x2(unsigned addr, unsigned& r0, unsigned& r1) {
    asm volatile("ldmatrix.sync.aligned.m8n8.x2.shared.b16 {%0,%1}, [%2];"
                 : "=r"(r0), "=r"(r1) : "r"(addr));
}

template<int AMODE, int OUTM, int CAUSAL>
__global__ __launch_bounds__(256, 2)
void mma_k(const __half* __restrict__ Ag, const __half* __restrict__ Bg,
           float* __restrict__ Cg, __half* __restrict__ Chg,
           int K, int lda, int ldb, int ldc, int Hdim,
           long sAb, long sAh, long sBb, long sBh, long sCb, long sCh) {
    extern __shared__ __align__(16) char smc[];

    const int zb = blockIdx.z / Hdim, zh = blockIdx.z % Hdim;
    const __half* A = Ag + zb * sAb + zh * sAh;
    const __half* B = Bg + zb * sBb + zh * sBh;
    float*  C  = Cg  + zb * sCb + zh * sCh;
    __half* Ch = Chg + zb * sCb + zh * sCh;

    const int row0 = blockIdx.y * 128, col0 = blockIdx.x * 128;
    const int tid = threadIdx.x, wid = tid >> 5, lane = tid & 31;
    const int warpM = (wid & 1) * 64, warpN = (wid >> 1) * 32;
    const int lr = lane >> 2, lc = lane & 3;

    float acc[4][4][4];
    #pragma unroll
    for (int im = 0; im < 4; im++)
        #pragma unroll
        for (int in = 0; in < 4; in++)
            #pragma unroll
            for (int q = 0; q < 4; q++) acc[im][in][q] = 0.f;

    const int nchh = CAUSAL ? min(8, 2 * (int)blockIdx.y + 2) : 1;
    const int nch  = CAUSAL ? H_ * nchh : K / MK;

    const unsigned sb32 = smem_u32(smc);
    const int lrow8 = lane & 7, sel = lane >> 3;
    const unsigned aoff = (unsigned)(((warpM + (sel & 1) * 8 + lrow8) * ROWH
                                      + (sel >> 1) * 8)) * 2u;
    const unsigned boff = (unsigned)(((warpN + lrow8) * ROWH
                                      + ((lane >> 3) & 1) * 8)) * 2u;

    auto issue = [&](int c) {
        unsigned sa = sb32 + (unsigned)((c % NSTG) * 2 * STGB);
        int kA, kB;
        int hh = 0;
        if (CAUSAL) {
            hh = c / nchh;
            int cc = c - hh * nchh;
            kA = cc * MK;                 // within-head k for probs
            kB = hh * S_ + kA;            // global hk for Yt
        } else {
            kA = c * MK; kB = kA;
        }
        #pragma unroll
        for (int i = 0; i < 4; i++) {
            int u = i * 256 + tid;
            int r = u >> 3, q = u & 7;    // row 0..127, 16B-quad 0..7
            const __half* srcA;
            if (AMODE == 0) srcA = A + (long)(row0 + r) * lda + kA + q * 8;
            else            srcA = A + (long)hh * (S_ * S_) + (long)(row0 + r) * S_ + kA + q * 8;
            unsigned off = (unsigned)(r * ROWH + q * 8) * 2u;
            cpasync16(sa + off, srcA);
            cpasync16(sa + (unsigned)STGB + off, B + (long)(col0 + r) * ldb + kB + q * 8);
        }
    };

    issue(0);
    asm volatile("cp.async.commit_group;" ::: "memory");
    issue(1);
    asm volatile("cp.async.commit_group;" ::: "memory");

    for (int c = 0; c < nch; c++) {
        asm volatile("cp.async.wait_group 1;" ::: "memory");
        __syncthreads();
        if (c + 2 < nch) issue(c + 2);
        asm volatile("cp.async.commit_group;" ::: "memory");  // one group/iter (maybe empty)

        const unsigned sAa = sb32 + (unsigned)((c % NSTG) * 2 * STGB);
        const unsigned sBa = sAa + (unsigned)STGB;
        #pragma unroll
        for (int ks = 0; ks < 4; ks++) {
            unsigned af[4][4], bf[4][2];
            #pragma unroll
            for (int im = 0; im < 4; im++)
                ldsm_x4(sAa + aoff + (unsigned)((im * 16 * ROWH + ks * 16) * 2),
                        af[im][0], af[im][1], af[im][2], af[im][3]);
            #pragma unroll
            for (int in = 0; in < 4; in++)
                ldsm_x2(sBa + boff + (unsigned)((in * 8 * ROWH + ks * 16) * 2),
                        bf[in][0], bf[in][1]);
            #pragma unroll
            for (int im = 0; im < 4; im++)
                #pragma unroll
                for (int in = 0; in < 4; in++) {
                    asm volatile(
                        "mma.sync.aligned.m16n8k16.row.col.f32.f16.f16.f32 "
                        "{%0,%1,%2,%3}, {%4,%5,%6,%7}, {%8,%9}, {%0,%1,%2,%3};"
                        : "+f"(acc[im][in][0]), "+f"(acc[im][in][1]),
                          "+f"(acc[im][in][2]), "+f"(acc[im][in][3])
                        : "r"(af[im][0]), "r"(af[im][1]), "r"(af[im][2]), "r"(af[im][3]),
                          "r"(bf[in][0]), "r"(bf[in][1]));
                }
        }
    }

    // epilogue: c0,c1 at (r, cc..cc+1); c2,c3 at (r+8, cc..cc+1)
    #pragma unroll
    for (int im = 0; im < 4; im++) {
        int r = row0 + warpM + im * 16 + lr;
        #pragma unroll
        for (int in = 0; in < 4; in++) {
            int cc = col0 + warpN + in * 8 + lc * 2;
            float v0 = acc[im][in][0], v1 = acc[im][in][1];
            float v2 = acc[im][in][2], v3 = acc[im][in][3];
            if (OUTM == 0 || OUTM == 2) {
                *reinterpret_cast<float2*>(C + (long)r * ldc + cc) = make_float2(v0, v1);
                *reinterpret_cast<float2*>(C + (long)(r + 8) * ldc + cc) = make_float2(v2, v3);
            }
            if (OUTM == 1 || OUTM == 2) {
                *reinterpret_cast<__half2*>(Ch + (long)r * ldc + cc) =
                    __floats2half2_rn(v0, v1);
                *reinterpret_cast<__half2*>(Ch + (long)(r + 8) * ldc + cc) =
                    __floats2half2_rn(v2, v3);
            }
        }
    }
}

// ---------- sparse vw: vwval[h][j] = A1[h][f,:] . WdecT[g_j,:]  (fp32) -------
#define GPG 4

__global__ __launch_bounds__(256)
void vw_sparse_k() {
    __shared__ float sA[H_][D_];   // 36 KB
    const int f = blockIdx.x;
    const int tid = threadIdx.x, wid = tid >> 5, lane = tid & 31;

    for (int i = tid; i < H_ * D_; i += 256) {
        int h = i / D_, m = i - h * D_;
        sA[h][m] = g_A1[((long)h * F_ + f) * D_ + m];
    }
    __syncthreads();

    int jb = g_rowptr[f], je = g_rowptr[f + 1];
    if (je > NNZCAP) je = NNZCAP;

    for (int j0 = jb + wid * GPG; j0 < je; j0 += 8 * GPG) {
        const int ng = min(GPG, je - j0);
        int gi[GPG];
        #pragma unroll
        for (int q = 0; q < GPG; q++)
            gi[q] = g_gidx[(q < ng) ? (j0 + q) : j0];

        float acc[GPG][H_];
        #pragma unroll
        for (int q = 0; q < GPG; q++)
            #pragma unroll
            for (int h = 0; h < H_; h++) acc[q][h] = 0.f;

        #pragma unroll
        for (int rep = 0; rep < 6; rep++) {
            const int m0 = rep * 128 + lane * 4;
            float4 wd[GPG];
            #pragma unroll
            for (int q = 0; q < GPG; q++)
                wd[q] = *reinterpret_cast<const float4*>(&g_WdecT[(long)gi[q] * D_ + m0]);
            #pragma unroll
            for (int h = 0; h < H_; h++) {
                float4 a = *reinterpret_cast<const float4*>(&sA[h][m0]);
                #pragma unroll
                for (int q = 0; q < GPG; q++) {
                    acc[q][h] += a.x * wd[q].x;
                    acc[q][h] += a.y * wd[q].y;
                    acc[q][h] += a.z * wd[q].z;
                    acc[q][h] += a.w * wd[q].w;
                }
            }
        }

        #pragma unroll
        for (int off = 16; off > 0; off >>= 1)
            #pragma unroll
            for (int q = 0; q < GPG; q++)
                #pragma unroll
                for (int h = 0; h < H_; h++)
                    acc[q][h] += __shfl_xor_sync(0xffffffffu, acc[q][h], off);

        #pragma unroll
        for (int q = 0; q < GPG; q++)
            #pragma unroll
            for (int h = 0; h < H_; h++) {
                int v = q * H_ + h;
                if ((v & 31) == lane && q < ng)
                    g_vwval[(long)h * NNZCAP + j0 + q] = acc[q][h];
            }
    }
}

// ---------------- spMM: YtH[b,f,h*S+k] += sum_j uplnT[gidx[j],bk]*vwval[h,j] -
constexpr int FT2 = 8;

__global__ __launch_bounds__(256)
void spmm_k() {
    const int t = threadIdx.x;
    const int bk = blockIdx.x * 256 + t;
    const int f0 = blockIdx.y * FT2;

    float acc[FT2][H_];
    #pragma unroll
    for (int i = 0; i < FT2; i++)
        #pragma unroll
        for (int h = 0; h < H_; h++) acc[i][h] = 0.f;

    #pragma unroll 1
    for (int fi = 0; fi < FT2; fi++) {
        const int f = f0 + fi;
        int j = g_rowptr[f];
        int je = g_rowptr[f + 1];
        if (je > NNZCAP) je = NNZCAP;
        for (; j + 1 < je; j += 2) {
            int   ga = g_gidx[j], gb = g_gidx[j + 1];
            float xa = g_uplnT[(long)ga * BS_ + bk];
            float xb = g_uplnT[(long)gb * BS_ + bk];
            #pragma unroll
            for (int h = 0; h < H_; h++) {
                const float* vp = g_vwval + (long)h * NNZCAP + j;
                acc[fi][h] += xa * vp[0];
                acc[fi][h] += xb * vp[1];
            }
        }
        for (; j < je; j++) {
            int g = g_gidx[j];
            float x = g_uplnT[(long)g * BS_ + bk];
            #pragma unroll
            for (int h = 0; h < H_; h++)
                acc[fi][h] += x * g_vwval[(long)h * NNZCAP + j];
        }
    }

    const int b = bk >> 9, k = bk & (S_ - 1);
    #pragma unroll 1
    for (int fi = 0; fi < FT2; fi++) {
        long base = ((long)b * F_ + f0 + fi) * HK_ + k;
        #pragma unroll
        for (int h = 0; h < H_; h++) {
            float y = __half2float(g_YtH[base + h * S_]) + acc[fi][h];
            g_YtH[base + h * S_] = __float2half(y);
        }
    }
}

// ---------------------------------------------------------------------------
extern "C" void kernel_launch(void* const* d_in, const int* in_sizes, int n_in,
                              void* d_out, int out_size) {
    (void)in_sizes; (void)n_in; (void)out_size;
    const float* act   = (const float*)d_in[0];
    const float* lns   = (const float*)d_in[1];
    const float* probs = (const float*)d_in[2];
    const float* pf    = (const float*)d_in[3];
    const float* W_O   = (const float*)d_in[4];
    const float* W_V   = (const float*)d_in[5];
    const float* W_enc = (const float*)d_in[6];
    const float* b_enc = (const float*)d_in[7];
    const float* b_dec = (const float*)d_in[8];
    const float* W_dec = (const float*)d_in[9];
    const float* upb   = (const float*)d_in[10];
    const unsigned char* mask = (const unsigned char*)d_in[11];
    float* out = (float*)d_out;

    float *WOV, *A1;
    __half *WOVh, *A1h, *WeH, *xlnH, *pH, *YtH;
    cudaGetSymbolAddress((void**)&WOV,  g_WOV);
    cudaGetSymbolAddress((void**)&WOVh, g_WOVh);
    cudaGetSymbolAddress((void**)&A1,   g_A1);
    cudaGetSymbolAddress((void**)&A1h,  g_A1h);
    cudaGetSymbolAddress((void**)&WeH,  g_WencH);
    cudaGetSymbolAddress((void**)&xlnH, g_xlnH);
    cudaGetSymbolAddress((void**)&pH,   g_probsH);
    cudaGetSymbolAddress((void**)&YtH,  g_YtH);

    const long DD = (long)D_ * D_;
    const long FD = (long)F_ * D_;
    const long SD = (long)S_ * D_;
    const long SS = (long)S_ * S_;
    const long FHK = (long)F_ * HK_;

    cudaFuncSetAttribute(mma_k<0, 2, 0>, cudaFuncAttributeMaxDynamicSharedMemorySize, MMA_SMEM);
    cudaFuncSetAttribute(mma_k<0, 1, 0>, cudaFuncAttributeMaxDynamicSharedMemorySize, MMA_SMEM);
    cudaFuncSetAttribute(mma_k<1, 0, 1>, cudaFuncAttributeMaxDynamicSharedMemorySize, MMA_SMEM);

    detect_mask_k<<<1, 256>>>(mask);
    count_k<<<(F_ * 32 + 255) / 256, 256>>>(mask);
    scan_k<<<1, 256>>>();
    fill_k<<<(F_ * 32 + 255) / 256, 256>>>(mask);

    {
        long tot = (long)B_ * S_ * D_;
        prep_x_k<<<(int)((tot + 255) / 256), 256>>>(act, lns);
    }
    half_wenc_k<<<(int)(((long)F_ * D_ + 255) / 256), 256>>>(W_enc);
    half_probs_k<<<(int)(((long)B_ * H_ * S_ * S_ + 255) / 256), 256>>>(probs);
    prep_upT_k<<<dim3(F_ / 32, BS_ / 32), dim3(32, 8)>>>(pf, lns);
    tpose_wdec_k<<<dim3(F_ / 32, D_ / 32), dim3(32, 8)>>>(W_dec);

    // 1) W_OV[h] = W_V[h] @ W_O[h]   (FFMA fp32) + half copy
    sgemm_nn_k<<<dim3(D_ / BN, D_ / BM, H_), 256>>>(
        W_V, W_O, WOV, DH_, DH_, D_, D_,
        (long)D_ * DH_, (long)DH_ * D_, DD);
    half_wov_k<<<(int)(((long)H_ * D_ * D_ + 255) / 256), 256>>>();

    c_k<<<dim3(3, H_, 8), 256>>>(upb);
    bias_vec_k<<<F_ / 256, 256>>>(W_enc, b_enc, b_dec);

    // 3) A1[h][f][m] = WencH[f,:] . WOVh[h][m,:]   M=2048 N=768 K=768 (fp32+half out)
    mma_k<0, 2, 0><<<dim3(D_ / 128, F_ / 128, H_), 256, MMA_SMEM>>>(
        WeH, WOVh, A1, A1h, D_, D_, D_, D_, H_,
        0, 0, 0, DD, 0, FD);

    // 4) sparse vw: vwval[h][j] = A1[h][f,:] . WdecT[g_j,:]  (fp32 direct)
    vw_sparse_k<<<F_, 256>>>();

    // 5a) YtH[b][f][h*S+k] = A1h[h][f,:] . xlnH[b][k,:]   M=2048 N=512 K=768 (half out)
    mma_k<0, 1, 0><<<dim3(S_ / 128, F_ / 128, B_ * H_), 256, MMA_SMEM>>>(
        A1h, xlnH, out /*dummy*/, YtH, D_, D_, D_, HK_, H_,
        0, FD, SD, 0, FHK, (long)S_);

    // 5b) sparse accumulate into YtH
    spmm_k<<<dim3(BS_ / 256, F_ / FT2), 256>>>();

    // 6) out[b][q][f] = probsH[b][q,:] . YtH[b][f,:]  causal-skip, K=6144 (fp32 out)
    mma_k<1, 0, 1><<<dim3(F_ / 128, S_ / 128, B_), 256, MMA_SMEM>>>(
        pH, YtH, out, YtH /*dummy*/, HK_, 0, HK_, F_, 1,
        (long)H_ * SS, 0, FHK, 0, (long)S_ * F_, 0);

    // 7) out += bias0[f] + e[f] / ln_scale
    {
        long tot = (long)B_ * S_ * F_;
        finish_k<<<(int)((tot + 255) / 256), 256>>>(out, lns);
    }
}

// round 9
// speedup vs baseline: 7.8701x; 1.3471x over previous
#include <cuda_runtime.h>
#include <cuda_fp16.h>

// Problem constants
#define B_  4
#define S_  512
#define D_  768
#define H_  12
#define DH_ 64
#define F_  2048
#define BS_ (B_ * S_)          // 2048
#define HK_ (H_ * S_)          // 6144
#define HD_ (H_ * DH_)         // 768  (flattened head dim)
#define NNZCAP 262144          // cap on mask nonzeros (expected ~210K)

// ---------------- scratch (device globals; no allocations allowed) ----------
__device__ __half g_WOh  [HD_ * D_];          // W_O flat [h*64+dh][d] half
__device__ __half g_WvTh [HD_ * D_];          // W_V^T flat [h*64+dh][m] half
__device__ __half g_WdecTh[F_ * D_];          // [g][m] half
__device__ __half g_WencH[F_ * D_];           // half W_enc
__device__ float  g_E1   [F_ * HD_];          // [f][h*64+dh] fp32
__device__ __half g_E1h  [F_ * HD_];          // half copy (GEMM operand)
__device__ float  g_wd2  [F_ * HD_];          // [g][h*64+dh] fp32
__device__ __half g_xlnH [B_ * S_ * D_];      // half x_ln
__device__ __half g_xvH  [B_ * S_ * HD_];     // [b][k][h*64+dh] half
__device__ __half g_probsH[B_ * H_ * S_ * S_];// half probs
__device__ float  g_uplnT[F_ * BS_];          // [g][bk] fp32
__device__ __half g_YtH  [B_ * F_ * HK_];     // [b][f][h*S+k] half
__device__ float  g_vwval[H_ * NNZCAP];       // fp32 compact masked vw
__device__ int    g_gidx [NNZCAP];
__device__ int    g_cnt  [F_];
__device__ int    g_rowptr[F_ + 1];
__device__ float  g_t    [HD_];               // W_V^T . upb
__device__ float  g_c    [D_];
__device__ float  g_bias0[F_];
__device__ float  g_e    [F_];
__device__ int    g_maskmode;

// ---------------- mask dtype detector (parallel) -----------------------------
__global__ void detect_mask_k(const unsigned char* __restrict__ m) {
    __shared__ int sF, sB;
    int tid = threadIdx.x;
    if (tid == 0) { sF = 0; sB = 0; }
    __syncthreads();
    int f = 0, b = 0;
    for (int i = tid; i < 65536; i += 256) {
        unsigned char v = m[i];
        if (v == 63 || v == 128) f = 1;
        else if (v != 0 && (i & 3) != 0) b = 1;
    }
    if (f) atomicOr(&sF, 1);
    if (b) atomicOr(&sB, 1);
    __syncthreads();
    if (tid == 0) g_maskmode = sF ? 2 : (sB ? 0 : 1);
}

__device__ __forceinline__ int mask_nz(const unsigned char* m, long idx, int mode) {
    if (mode == 0) return m[idx] != 0;
    if (mode == 1) return ((const int*)m)[idx] != 0;
    return ((const float*)m)[idx] != 0.f;
}

// ---------------- mask CSR builders -----------------------------------------
__global__ void count_k(const unsigned char* __restrict__ m) {
    int w = (blockIdx.x * blockDim.x + threadIdx.x) >> 5;
    int lane = threadIdx.x & 31;
    if (w >= F_) return;
    int mode = g_maskmode;
    int cnt = 0;
    for (int g0 = 0; g0 < F_; g0 += 32) {
        int v = mask_nz(m, (long)w * F_ + g0 + lane, mode);
        cnt += __popc(__ballot_sync(0xffffffffu, v));
    }
    if (lane == 0) g_cnt[w] = cnt;
}

__global__ void scan_k() {
    __shared__ int part[256];
    int t = threadIdx.x;
    int base = t * 8;
    int s = 0;
    for (int i = 0; i < 8; i++) s += g_cnt[base + i];
    part[t] = s;
    __syncthreads();
    if (t == 0) {
        int r = 0;
        for (int i = 0; i < 256; i++) { int v = part[i]; part[i] = r; r += v; }
        g_rowptr[F_] = r;
    }
    __syncthreads();
    int r = part[t];
    for (int i = 0; i < 8; i++) { g_rowptr[base + i] = r; r += g_cnt[base + i]; }
}

__global__ void fill_k(const unsigned char* __restrict__ m) {
    int w = (blockIdx.x * blockDim.x + threadIdx.x) >> 5;
    int lane = threadIdx.x & 31;
    if (w >= F_) return;
    int mode = g_maskmode;
    int base = g_rowptr[w];
    unsigned lt = (1u << lane) - 1u;
    for (int g0 = 0; g0 < F_; g0 += 32) {
        int g = g0 + lane;
        int v = mask_nz(m, (long)w * F_ + g, mode);
        unsigned bal = __ballot_sync(0xffffffffu, v);
        int pos = base + __popc(bal & lt);
        if (v && pos < NNZCAP) g_gidx[pos] = g;
        base += __popc(bal);
    }
}

// ---------------- elementwise prep ------------------------------------------
__global__ void prep_x_k(const float* __restrict__ act, const float* __restrict__ lns) {
    long i = (long)blockIdx.x * blockDim.x + threadIdx.x;
    if (i < (long)B_ * S_ * D_) g_xlnH[i] = __float2half(act[i] / lns[i / D_]);
}

__global__ void half_wenc_k(const float* __restrict__ w) {
    long i = (long)blockIdx.x * blockDim.x + threadIdx.x;
    if (i < (long)F_ * D_) g_WencH[i] = __float2half(w[i]);
}
__global__ void half_probs_k(const float* __restrict__ p) {
    long i = (long)blockIdx.x * blockDim.x + threadIdx.x;
    if (i < (long)B_ * H_ * S_ * S_) g_probsH[i] = __float2half(p[i]);
}
__global__ void half_wo_k(const float* __restrict__ wo) {
    long i = (long)blockIdx.x * blockDim.x + threadIdx.x;
    if (i < (long)HD_ * D_) g_WOh[i] = __float2half(wo[i]);
}

// W_V [h][m][dh] -> WvTh[h*64+dh][m] half
__global__ void tpose_wv_k(const float* __restrict__ wv) {
    __shared__ float tile[32][33];
    int tx = threadIdx.x, ty = threadIdx.y;
    int h = blockIdx.z;
    int m0 = blockIdx.x * 32, dh0 = blockIdx.y * 32;
    #pragma unroll
    for (int i = 0; i < 32; i += 8)
        tile[ty + i][tx] = wv[((long)h * D_ + m0 + ty + i) * DH_ + dh0 + tx];
    __syncthreads();
    #pragma unroll
    for (int i = 0; i < 32; i += 8)
        g_WvTh[((long)h * DH_ + dh0 + ty + i) * D_ + m0 + tx] =
            __float2half(tile[tx][ty + i]);
}

// W_decT[g][m] = W_dec[m][g]   half
__global__ void tpose_wdec_k(const float* __restrict__ wd) {
    __shared__ float tile[32][33];
    int tx = threadIdx.x, ty = threadIdx.y;
    int g = blockIdx.x * 32 + tx;
    int m0 = blockIdx.y * 32;
    #pragma unroll
    for (int i = 0; i < 32; i += 8)
        tile[ty + i][tx] = wd[(long)(m0 + ty + i) * F_ + g];
    __syncthreads();
    int mOut = m0 + tx;
    #pragma unroll
    for (int i = 0; i < 32; i += 8)
        g_WdecTh[(long)(blockIdx.x * 32 + ty + i) * D_ + mOut] =
            __float2half(tile[tx][ty + i]);
}

__global__ void prep_upT_k(const float* __restrict__ pf, const float* __restrict__ lns) {
    __shared__ float tile[32][33];
    int tx = threadIdx.x, ty = threadIdx.y;
    int g = blockIdx.x * 32 + tx;
    int bk0 = blockIdx.y * 32;
    #pragma unroll
    for (int i = 0; i < 32; i += 8) {
        int bk = bk0 + ty + i;
        tile[ty + i][tx] = pf[(long)bk * F_ + g] / lns[bk];
    }
    __syncthreads();
    int bkOut = bk0 + tx;
    #pragma unroll
    for (int i = 0; i < 32; i += 8)
        g_uplnT[(long)(blockIdx.x * 32 + ty + i) * BS_ + bkOut] = tile[tx][ty + i];
}

// ---------------- bias vectors (rank-64 path) --------------------------------
// t[h*64+dh] = sum_m W_V[h][m][dh] * upb[m]
__global__ void t_k(const float* __restrict__ wv, const float* __restrict__ upb) {
    int h = blockIdx.x, dh = threadIdx.x;   // grid H_, block 64
    float s = 0.f;
    for (int m = 0; m < D_; m++)
        s += wv[((long)h * D_ + m) * DH_ + dh] * upb[m];
    g_t[h * DH_ + dh] = s;
}
// c[d] = sum_{hdh} W_O[hdh][d] * t[hdh]
__global__ void c2_k(const float* __restrict__ wo) {
    int d = blockIdx.x * 256 + threadIdx.x;  // grid 3, block 256
    if (d >= D_) return;
    float s = 0.f;
    for (int i = 0; i < HD_; i++) s += wo[(long)i * D_ + d] * g_t[i];
    g_c[d] = s;
}

__global__ void bias_vec_k(const float* __restrict__ W_enc,
                           const float* __restrict__ b_enc,
                           const float* __restrict__ b_dec) {
    int f = blockIdx.x * 256 + threadIdx.x;
    if (f >= F_) return;
    const float* row = W_enc + (long)f * D_;
    float s0 = 0.f, s1 = 0.f;
    for (int d = 0; d < D_; d++) {
        float w = row[d];
        s0 += w * b_dec[d];
        s1 += w * g_c[d];
    }
    g_bias0[f] = b_enc[f] - s0;
    g_e[f] = s1;
}

__global__ void finish_k(float* __restrict__ out, const float* __restrict__ lns) {
    long i = (long)blockIdx.x * blockDim.x + threadIdx.x;
    if (i >= (long)B_ * S_ * F_) return;
    int f = (int)(i & (F_ - 1));
    long row = i >> 11;
    out[i] += g_bias0[f] + g_e[f] / lns[row];
}

// ====== fp16 mma.sync m16n8k16 GEMM, cp.async 3-stage + ldmatrix (NT) ========
// C[M,N] = A[M,K] * B[N,K]^T, fp16 in / fp32 acc.
// Block 128x128, K-chunk 64 (4 k-steps of 16), 8 warps 2(M)x4(N).
// AMODE 0: A row-major [M,K] lda.  AMODE 1: A = probsH[b] piecewise per head.
// OUTM 0: fp32 C.  1: half Ch.  2: both.
// CAUSAL 1 (with AMODE 1): per q-block keep only k-chunks with k < row0+128.
#define MK   64
#define ROWH 72                               // halfs per smem row (64 + 8 pad)
#define NSTG 3
#define STGB (128 * ROWH * 2)                 // bytes per operand stage (18432)
#define MMA_SMEM (NSTG * 2 * STGB)            // 110592 bytes

__device__ __forceinline__ unsigned smem_u32(const void* p) {
    unsigned a;
    asm("{ .reg .u64 t; cvta.to.shared.u64 t, %1; cvt.u32.u64 %0, t; }" : "=r"(a) : "l"(p));
    return a;
}
__device__ __forceinline__ void cpasync16(unsigned dst, const void* src) {
    asm volatile("cp.async.cg.shared.global [%0], [%1], 16;" :: "r"(dst), "l"(src) : "memory");
}
__device__ __forceinline__ void ldsm_x4(unsigned addr, unsigned& r0, unsigned& r1,
                                        unsigned& r2, unsigned& r3) {
    asm volatile("ldmatrix.sync.aligned.m8n8.x4.shared.b16 {%0,%1,%2,%3}, [%4];"
                 : "=r"(r0), "=r"(r1), "=r"(r2), "=r"(r3) : "r"(addr));
}
__device__ __forceinline__ void ldsm_x2(unsigned addr, unsigned& r0, unsigned& r1) {
    asm volatile("ldmatrix.sync.aligned.m8n8.x2.shared.b16 {%0,%1}, [%2];"
                 : "=r"(r0), "=r"(r1) : "r"(addr));
}

template<int AMODE, int OUTM, int CAUSAL>
__global__ __launch_bounds__(256, 2)
void mma_k(const __half* __restrict__ Ag, const __half* __restrict__ Bg,
           float* __restrict__ Cg, __half* __restrict__ Chg,
           int K, int lda, int ldb, int ldc, int Hdim,
           long sAb, long sAh, long sBb, long sBh, long sCb, long sCh) {
    extern __shared__ __align__(16) char smc[];

    const int zb = blockIdx.z / Hdim, zh = blockIdx.z % Hdim;
    const __half* A = Ag + zb * sAb + zh * sAh;
    const __half* B = Bg + zb * sBb + zh * sBh;
    float*  C  = Cg  + zb * sCb + zh * sCh;
    __half* Ch = Chg + zb * sCb + zh * sCh;

    const int row0 = blockIdx.y * 128, col0 = blockIdx.x * 128;
    const int tid = threadIdx.x, wid = tid >> 5, lane = tid & 31;
    const int warpM = (wid & 1) * 64, warpN = (wid >> 1) * 32;
    const int lr = lane >> 2, lc = lane & 3;

    float acc[4][4][4];
    #pragma unroll
    for (int im = 0; im < 4; im++)
        #pragma unroll
        for (int in = 0; in < 4; in++)
            #pragma unroll
            for (int q = 0; q < 4; q++) acc[im][in][q] = 0.f;

    const int nchh = CAUSAL ? min(8, 2 * (int)blockIdx.y + 2) : 1;
    const int nch  = CAUSAL ? H_ * nchh : K / MK;

    const unsigned sb32 = smem_u32(smc);
    const int lrow8 = lane & 7, sel = lane >> 3;
    const unsigned aoff = (unsigned)(((warpM + (sel & 1) * 8 + lrow8) * ROWH
                                      + (sel >> 1) * 8)) * 2u;
    const unsigned boff = (unsigned)(((warpN + lrow8) * ROWH
                                      + ((lane >> 3) & 1) * 8)) * 2u;

    auto issue = [&](int c) {
        unsigned sa = sb32 + (unsigned)((c % NSTG) * 2 * STGB);
        int kA, kB;
        int hh = 0;
        if (CAUSAL) {
            hh = c / nchh;
            int cc = c - hh * nchh;
            kA = cc * MK;                 // within-head k for probs
            kB = hh * S_ + kA;            // global hk for Yt
        } else {
            kA = c * MK; kB = kA;
        }
        #pragma unroll
        for (int i = 0; i < 4; i++) {
            int u = i * 256 + tid;
            int r = u >> 3, q = u & 7;    // row 0..127, 16B-quad 0..7
            const __half* srcA;
            if (AMODE == 0) srcA = A + (long)(row0 + r) * lda + kA + q * 8;
            else            srcA = A + (long)hh * (S_ * S_) + (long)(row0 + r) * S_ + kA + q * 8;
            unsigned off = (unsigned)(r * ROWH + q * 8) * 2u;
            cpasync16(sa + off, srcA);
            cpasync16(sa + (unsigned)STGB + off, B + (long)(col0 + r) * ldb + kB + q * 8);
        }
    };

    issue(0);
    asm volatile("cp.async.commit_group;" ::: "memory");
    if (nch > 1) issue(1);
    asm volatile("cp.async.commit_group;" ::: "memory");

    for (int c = 0; c < nch; c++) {
        asm volatile("cp.async.wait_group 1;" ::: "memory");
        __syncthreads();
        if (c + 2 < nch) issue(c + 2);
        asm volatile("cp.async.commit_group;" ::: "memory");  // one group/iter (maybe empty)

        const unsigned sAa = sb32 + (unsigned)((c % NSTG) * 2 * STGB);
        const unsigned sBa = sAa + (unsigned)STGB;
        #pragma unroll
        for (int ks = 0; ks < 4; ks++) {
            unsigned af[4][4], bf[4][2];
            #pragma unroll
            for (int im = 0; im < 4; im++)
                ldsm_x4(sAa + aoff + (unsigned)((im * 16 * ROWH + ks * 16) * 2),
                        af[im][0], af[im][1], af[im][2], af[im][3]);
            #pragma unroll
            for (int in = 0; in < 4; in++)
                ldsm_x2(sBa + boff + (unsigned)((in * 8 * ROWH + ks * 16) * 2),
                        bf[in][0], bf[in][1]);
            #pragma unroll
            for (int im = 0; im < 4; im++)
                #pragma unroll
                for (int in = 0; in < 4; in++) {
                    asm volatile(
                        "mma.sync.aligned.m16n8k16.row.col.f32.f16.f16.f32 "
                        "{%0,%1,%2,%3}, {%4,%5,%6,%7}, {%8,%9}, {%0,%1,%2,%3};"
                        : "+f"(acc[im][in][0]), "+f"(acc[im][in][1]),
                          "+f"(acc[im][in][2]), "+f"(acc[im][in][3])
                        : "r"(af[im][0]), "r"(af[im][1]), "r"(af[im][2]), "r"(af[im][3]),
                          "r"(bf[in][0]), "r"(bf[in][1]));
                }
        }
    }

    // epilogue: c0,c1 at (r, cc..cc+1); c2,c3 at (r+8, cc..cc+1)
    #pragma unroll
    for (int im = 0; im < 4; im++) {
        int r = row0 + warpM + im * 16 + lr;
        #pragma unroll
        for (int in = 0; in < 4; in++) {
            int cc = col0 + warpN + in * 8 + lc * 2;
            float v0 = acc[im][in][0], v1 = acc[im][in][1];
            float v2 = acc[im][in][2], v3 = acc[im][in][3];
            if (OUTM == 0 || OUTM == 2) {
                *reinterpret_cast<float2*>(C + (long)r * ldc + cc) = make_float2(v0, v1);
                *reinterpret_cast<float2*>(C + (long)(r + 8) * ldc + cc) = make_float2(v2, v3);
            }
            if (OUTM == 1 || OUTM == 2) {
                *reinterpret_cast<__half2*>(Ch + (long)r * ldc + cc) =
                    __floats2half2_rn(v0, v1);
                *reinterpret_cast<__half2*>(Ch + (long)(r + 8) * ldc + cc) =
                    __floats2half2_rn(v2, v3);
            }
        }
    }
}

// ---------- sparse vw: vwval[h][j] = sum_dh E1[f][h64+dh] * wd2[g][h64+dh] ---
// block per f; thread per (j-local, h); 64-long fp32 dots, no reduction.
__global__ __launch_bounds__(256)
void vw_sparse_k() {
    __shared__ float sE[HD_];
    const int f = blockIdx.x;
    const int tid = threadIdx.x;

    for (int i = tid; i < HD_; i += 256) sE[i] = g_E1[(long)f * HD_ + i];
    __syncthreads();

    const int jb = g_rowptr[f];
    int je = g_rowptr[f + 1];
    if (je > NNZCAP) je = NNZCAP;

    const int jl = tid / H_, h = tid - jl * H_;   // 21 j-slots x 12 heads = 252
    if (tid >= 252) return;

    for (int j = jb + jl; j < je; j += 21) {
        const int g = g_gidx[j];
        const float* w = g_wd2 + (long)g * HD_ + h * DH_;
        const float* e = sE + h * DH_;
        float s = 0.f;
        #pragma unroll
        for (int d = 0; d < DH_; d += 4) {
            float4 wv = *reinterpret_cast<const float4*>(w + d);
            float4 ev = *reinterpret_cast<const float4*>(e + d);
            s += ev.x * wv.x + ev.y * wv.y + ev.z * wv.z + ev.w * wv.w;
        }
        g_vwval[(long)h * NNZCAP + j] = s;
    }
}

// ---------------- spMM: YtH[b,f,h*S+k] += sum_j uplnT[gidx[j],bk]*vwval[h,j] -
constexpr int FT2 = 8;

__global__ __launch_bounds__(256)
void spmm_k() {
    const int t = threadIdx.x;
    const int bk = blockIdx.x * 256 + t;
    const int f0 = blockIdx.y * FT2;

    float acc[FT2][H_];
    #pragma unroll
    for (int i = 0; i < FT2; i++)
        #pragma unroll
        for (int h = 0; h < H_; h++) acc[i][h] = 0.f;

    #pragma unroll 1
    for (int fi = 0; fi < FT2; fi++) {
        const int f = f0 + fi;
        int j = g_rowptr[f];
        int je = g_rowptr[f + 1];
        if (je > NNZCAP) je = NNZCAP;
        for (; j + 1 < je; j += 2) {
            int   ga = g_gidx[j], gb = g_gidx[j + 1];
            float xa = g_uplnT[(long)ga * BS_ + bk];
            float xb = g_uplnT[(long)gb * BS_ + bk];
            #pragma unroll
            for (int h = 0; h < H_; h++) {
                const float* vp = g_vwval + (long)h * NNZCAP + j;
                acc[fi][h] += xa * vp[0];
                acc[fi][h] += xb * vp[1];
            }
        }
        for (; j < je; j++) {
            int g = g_gidx[j];
            float x = g_uplnT[(long)g * BS_ + bk];
            #pragma unroll
            for (int h = 0; h < H_; h++)
                acc[fi][h] += x * g_vwval[(long)h * NNZCAP + j];
        }
    }

    const int b = bk >> 9, k = bk & (S_ - 1);
    #pragma unroll 1
    for (int fi = 0; fi < FT2; fi++) {
        long base = ((long)b * F_ + f0 + fi) * HK_ + k;
        #pragma unroll
        for (int h = 0; h < H_; h++) {
            float y = __half2float(g_YtH[base + h * S_]) + acc[fi][h];
            g_YtH[base + h * S_] = __float2half(y);
        }
    }
}

// ---------------------------------------------------------------------------
extern "C" void kernel_launch(void* const* d_in, const int* in_sizes, int n_in,
                              void* d_out, int out_size) {
    (void)in_sizes; (void)n_in; (void)out_size;
    const float* act   = (const float*)d_in[0];
    const float* lns   = (const float*)d_in[1];
    const float* probs = (const float*)d_in[2];
    const float* pf    = (const float*)d_in[3];
    const float* W_O   = (const float*)d_in[4];
    const float* W_V   = (const float*)d_in[5];
    const float* W_enc = (const float*)d_in[6];
    const float* b_enc = (const float*)d_in[7];
    const float* b_dec = (const float*)d_in[8];
    const float* W_dec = (const float*)d_in[9];
    const float* upb   = (const float*)d_in[10];
    const unsigned char* mask = (const unsigned char*)d_in[11];
    float* out = (float*)d_out;

    float *E1, *wd2;
    __half *WOh, *WvTh, *WdTh, *WeH, *xlnH, *E1h, *xvH, *pH, *YtH;
    cudaGetSymbolAddress((void**)&WOh,  g_WOh);
    cudaGetSymbolAddress((void**)&WvTh, g_WvTh);
    cudaGetSymbolAddress((void**)&WdTh, g_WdecTh);
    cudaGetSymbolAddress((void**)&WeH,  g_WencH);
    cudaGetSymbolAddress((void**)&E1,   g_E1);
    cudaGetSymbolAddress((void**)&E1h,  g_E1h);
    cudaGetSymbolAddress((void**)&wd2,  g_wd2);
    cudaGetSymbolAddress((void**)&xlnH, g_xlnH);
    cudaGetSymbolAddress((void**)&xvH,  g_xvH);
    cudaGetSymbolAddress((void**)&pH,   g_probsH);
    cudaGetSymbolAddress((void**)&YtH,  g_YtH);

    const long SD  = (long)S_ * D_;
    const long SS  = (long)S_ * S_;
    const long SHD = (long)S_ * HD_;
    const long FHK = (long)F_ * HK_;

    cudaFuncSetAttribute(mma_k<0, 0, 0>, cudaFuncAttributeMaxDynamicSharedMemorySize, MMA_SMEM);
    cudaFuncSetAttribute(mma_k<0, 1, 0>, cudaFuncAttributeMaxDynamicSharedMemorySize, MMA_SMEM);
    cudaFuncSetAttribute(mma_k<0, 2, 0>, cudaFuncAttributeMaxDynamicSharedMemorySize, MMA_SMEM);
    cudaFuncSetAttribute(mma_k<1, 0, 1>, cudaFuncAttributeMaxDynamicSharedMemorySize, MMA_SMEM);

    detect_mask_k<<<1, 256>>>(mask);
    count_k<<<(F_ * 32 + 255) / 256, 256>>>(mask);
    scan_k<<<1, 256>>>();
    fill_k<<<(F_ * 32 + 255) / 256, 256>>>(mask);

    prep_x_k<<<(int)(((long)B_ * S_ * D_ + 255) / 256), 256>>>(act, lns);
    half_wenc_k<<<(int)(((long)F_ * D_ + 255) / 256), 256>>>(W_enc);
    half_probs_k<<<(int)(((long)B_ * H_ * S_ * S_ + 255) / 256), 256>>>(probs);
    half_wo_k<<<(int)(((long)HD_ * D_ + 255) / 256), 256>>>(W_O);
    tpose_wv_k<<<dim3(D_ / 32, DH_ / 32, H_), dim3(32, 8)>>>(W_V);
    tpose_wdec_k<<<dim3(F_ / 32, D_ / 32), dim3(32, 8)>>>(W_dec);
    prep_upT_k<<<dim3(F_ / 32, BS_ / 32), dim3(32, 8)>>>(pf, lns);

    // bias vectors (rank-64)
    t_k<<<H_, DH_>>>(W_V, upb);
    c2_k<<<3, 256>>>(W_O);
    bias_vec_k<<<F_ / 256, 256>>>(W_enc, b_enc, b_dec);

    // E1[f][hdh] = WencH[f,:] . WOh[hdh,:]   M=2048 N=768 K=768 (fp32+half out)
    mma_k<0, 2, 0><<<dim3(HD_ / 128, F_ / 128, 1), 256, MMA_SMEM>>>(
        WeH, WOh, E1, E1h, D_, D_, D_, HD_, 1,
        0, 0, 0, 0, 0, 0);

    // wd2[g][hdh] = WdecTh[g,:] . WvTh[hdh,:]   M=2048 N=768 K=768 (fp32 out)
    mma_k<0, 0, 0><<<dim3(HD_ / 128, F_ / 128, 1), 256, MMA_SMEM>>>(
        WdTh, WvTh, wd2, E1h /*dummy*/, D_, D_, D_, HD_, 1,
        0, 0, 0, 0, 0, 0);

    // xv[b][k][hdh] = xlnH[b][k,:] . WvTh[hdh,:]   M=512 N=768 K=768 (half out)
    mma_k<0, 1, 0><<<dim3(HD_ / 128, S_ / 128, B_), 256, MMA_SMEM>>>(
        xlnH, WvTh, out /*dummy*/, xvH, D_, D_, D_, HD_, 1,
        SD, 0, 0, 0, SHD, 0);

    // sparse vw (needs E1 fp32 + wd2)
    vw_sparse_k<<<F_, 256>>>();

    // Yt[b,h][f][k] = E1h[f, h64:] . xv[b][k, h64:]   M=2048 N=512 K=64 (half out)
    mma_k<0, 1, 0><<<dim3(S_ / 128, F_ / 128, B_ * H_), 256, MMA_SMEM>>>(
        E1h, xvH, out /*dummy*/, YtH, DH_, HD_, HD_, HK_, H_,
        0, DH_, SHD, DH_, FHK, (long)S_);

    // sparse accumulate into YtH
    spmm_k<<<dim3(BS_ / 256, F_ / FT2), 256>>>();

    // out[b][q][f] = probsH[b][q,:] . YtH[b][f,:]  causal-skip, K=6144 (fp32 out)
    mma_k<1, 0, 1><<<dim3(F_ / 128, S_ / 128, B_), 256, MMA_SMEM>>>(
        pH, YtH, out, YtH /*dummy*/, HK_, 0, HK_, F_, 1,
        (long)H_ * SS, 0, FHK, 0, (long)S_ * F_, 0);

    // out += bias0[f] + e[f] / ln_scale
    finish_k<<<(int)(((long)B_ * S_ * F_ + 255) / 256), 256>>>(out, lns);
}